// round 1
// baseline (speedup 1.0000x reference)
#include <cuda_runtime.h>
#include <cuda_bf16.h>

// Problem constants (fixed by the dataset)
#define NN 100000
#define EE 3200000
#define NG 64
#define F_IN 128
#define H1 128
#define H2 64
#define DENSE 128
#define LABELS 2

// ---------------- scratch (__device__ globals; no runtime allocation) -------
__device__ float g_dis[NN];              // degree -> rsqrt(degree)
__device__ float g_h [(size_t)NN * 128]; // gemm outputs (h tmp / h2)
__device__ float g_agg[(size_t)NN * 128];// aggregation buffer
__device__ float g_h1[(size_t)NN * 128]; // relu(layer1) / a1
__device__ float g_gsum[NG * DENSE];
__device__ float g_gcnt[NG];

// ---------------- small elementwise kernels ---------------------------------
__global__ void k_init_deg(float* deg) {
    int i = blockIdx.x * blockDim.x + threadIdx.x;
    if (i < NN) deg[i] = 1.0f;   // self-loop
}

__global__ void k_deg_scatter(const int* __restrict__ dst, float* __restrict__ deg) {
    int i = blockIdx.x * blockDim.x + threadIdx.x;
    int stride = gridDim.x * blockDim.x;
    for (; i < EE; i += stride) atomicAdd(&deg[dst[i]], 1.0f);
}

__global__ void k_rsqrt(float* d) {
    int i = blockIdx.x * blockDim.x + threadIdx.x;
    if (i < NN) d[i] = rsqrtf(d[i]);
}

// agg = h * dis^2   (self-loop term), K = feature width
template<int K>
__global__ void k_self_init(const float* __restrict__ h, const float* __restrict__ dis,
                            float* __restrict__ agg) {
    size_t idx = (size_t)blockIdx.x * blockDim.x + threadIdx.x;
    size_t total = (size_t)NN * K;
    size_t stride = (size_t)gridDim.x * blockDim.x;
    for (; idx < total; idx += stride) {
        int node = (int)(idx / K);
        float d = dis[node];
        agg[idx] = h[idx] * d * d;
    }
}

// out = relu(agg + b)
template<int K>
__global__ void k_bias_relu(const float* __restrict__ agg, const float* __restrict__ b,
                            float* __restrict__ out) {
    size_t idx = (size_t)blockIdx.x * blockDim.x + threadIdx.x;
    size_t total = (size_t)NN * K;
    size_t stride = (size_t)gridDim.x * blockDim.x;
    for (; idx < total; idx += stride) {
        float v = agg[idx] + b[idx % K];
        out[idx] = v > 0.f ? v : 0.f;
    }
}

__global__ void k_zero_pool(float* gsum, float* gcnt) {
    int i = blockIdx.x * blockDim.x + threadIdx.x;
    if (i < NG * DENSE) gsum[i] = 0.f;
    if (i < NG) gcnt[i] = 0.f;
}

// ---------------- edge scatter: agg[dst] += h[src] * dis[src]*dis[dst] ------
template<int K>
__global__ void k_edge_scatter(const float* __restrict__ h, const float* __restrict__ dis,
                               const int* __restrict__ src, const int* __restrict__ dst,
                               float* __restrict__ agg) {
    constexpr int KF4 = K / 4;          // float4 lanes per edge
    constexpr int EPW = 32 / KF4;       // edges per warp
    int gtid = blockIdx.x * blockDim.x + threadIdx.x;
    int warp = gtid >> 5;
    int lane = threadIdx.x & 31;
    int sub  = lane / KF4;              // which edge within the warp
    int li   = lane % KF4;              // which float4 within the feature row
    long e = (long)warp * EPW + sub;
    long estride = ((long)gridDim.x * blockDim.x / 32) * EPW;
    for (; e < EE; e += estride) {
        int s = src[e];
        int d = dst[e];
        float coef = dis[s] * dis[d];
        float4 v = *(const float4*)(h + (size_t)s * K + li * 4);
        float* o = agg + (size_t)d * K + li * 4;
        atomicAdd(o + 0, v.x * coef);
        atomicAdd(o + 1, v.y * coef);
        atomicAdd(o + 2, v.z * coef);
        atomicAdd(o + 3, v.w * coef);
    }
}

// ---------------- GEMM: C[M,NC] = A[M,K] @ B[K,NC] (+bias) -----------------
// 64-row tiles, 256 threads, 4x(NC/16) register tile per thread, K chunked by 32.
template<int K, int NC, bool BIAS>
__global__ void k_gemm(const float* __restrict__ A, const float* __restrict__ B,
                       const float* __restrict__ bias, float* __restrict__ C, int M) {
    constexpr int MT  = 64;
    constexpr int KC  = 32;
    constexpr int KP  = KC + 4;         // pad: bank-conflict-free row access
    constexpr int CPT = NC / 16;        // cols per thread (8 or 4)
    __shared__ float sA[MT * KP];
    __shared__ float sB[KC * NC];

    int tid  = threadIdx.x;
    int row0 = blockIdx.x * MT;
    int rg = tid >> 4;                  // 0..15 row group
    int cg = tid & 15;                  // 0..15 col group
    int r0 = rg * 4;
    int c0 = cg * CPT;

    float acc[4][CPT];
#pragma unroll
    for (int i = 0; i < 4; i++)
#pragma unroll
        for (int j = 0; j < CPT; j++) acc[i][j] = 0.f;

    for (int kk = 0; kk < K; kk += KC) {
        // load A tile [MT x KC]
#pragma unroll
        for (int idx = tid * 4; idx < MT * KC; idx += 256 * 4) {
            int r = idx / KC, c = idx % KC;
            float4 v = make_float4(0.f, 0.f, 0.f, 0.f);
            if (row0 + r < M)
                v = *(const float4*)(A + (size_t)(row0 + r) * K + kk + c);
            *(float4*)(sA + r * KP + c) = v;
        }
        // load B tile [KC x NC]
#pragma unroll
        for (int idx = tid * 4; idx < KC * NC; idx += 256 * 4) {
            int r = idx / NC, c = idx % NC;
            *(float4*)(sB + idx) = *(const float4*)(B + (size_t)(kk + r) * NC + c);
        }
        __syncthreads();
#pragma unroll 4
        for (int k = 0; k < KC; k++) {
            float a[4];
#pragma unroll
            for (int i = 0; i < 4; i++) a[i] = sA[(r0 + i) * KP + k];
            float b[CPT];
#pragma unroll
            for (int j = 0; j < CPT; j += 4) {
                float4 bv = *(const float4*)(sB + k * NC + c0 + j);
                b[j] = bv.x; b[j + 1] = bv.y; b[j + 2] = bv.z; b[j + 3] = bv.w;
            }
#pragma unroll
            for (int i = 0; i < 4; i++)
#pragma unroll
                for (int j = 0; j < CPT; j++)
                    acc[i][j] += a[i] * b[j];
        }
        __syncthreads();
    }
#pragma unroll
    for (int i = 0; i < 4; i++) {
        int r = row0 + r0 + i;
        if (r < M) {
#pragma unroll
            for (int j = 0; j < CPT; j++) {
                float v = acc[i][j];
                if (BIAS) v += bias[c0 + j];
                C[(size_t)r * NC + c0 + j] = v;
            }
        }
    }
}

// ---------------- graph counts (warp-aggregated atomics; batch sorted) ------
__global__ void k_count(const int* __restrict__ batch, float* __restrict__ gcnt) {
    int i = blockIdx.x * blockDim.x + threadIdx.x;
    unsigned act = __ballot_sync(0xffffffffu, i < NN);
    if (i < NN) {
        int b = batch[i];
        unsigned m = __match_any_sync(act, b);
        int leader = __ffs(m) - 1;
        if ((threadIdx.x & 31) == leader)
            atomicAdd(&gcnt[b], (float)__popc(m));
    }
}

// ---------------- pooling: gsum[g] += sum_{batch[n]==g} a1[n] ---------------
// 256 contiguous nodes per block; batch sorted -> few graphs per block.
__global__ void k_pool(const float* __restrict__ a1, const int* __restrict__ batch,
                       float* __restrict__ gsum) {
    constexpr int RB = 256;
    __shared__ float sm[4][DENSE];
    __shared__ int s_gmin, s_ngr;
    int base = blockIdx.x * RB;
    int nrows = NN - base; if (nrows > RB) nrows = RB;
    int tid = threadIdx.x;
    if (tid == 0) {
        int gmin = batch[base];
        int gmax = batch[base + nrows - 1];
        s_gmin = gmin; s_ngr = gmax - gmin + 1;
    }
    for (int i = tid; i < 4 * DENSE; i += 256) ((float*)sm)[i] = 0.f;
    __syncthreads();
    int gmin = s_gmin, ngr = s_ngr;
    int col = tid & 127, half = tid >> 7;
    if (ngr <= 4) {
        int curg = -1; float acc = 0.f;
        for (int r = half; r < nrows; r += 2) {
            int node = base + r;
            int g = batch[node];
            float v = a1[(size_t)node * DENSE + col];
            if (g != curg) {
                if (curg >= 0) atomicAdd(&sm[curg - gmin][col], acc);
                curg = g; acc = v;
            } else acc += v;
        }
        if (curg >= 0) atomicAdd(&sm[curg - gmin][col], acc);
        __syncthreads();
        if (tid < DENSE)
            for (int s = 0; s < ngr; s++)
                atomicAdd(&gsum[(size_t)(gmin + s) * DENSE + col], sm[s][col]);
    } else { // general fallback (not hit with this data)
        for (int r = half; r < nrows; r += 2) {
            int node = base + r;
            atomicAdd(&gsum[(size_t)batch[node] * DENSE + col],
                      a1[(size_t)node * DENSE + col]);
        }
    }
}

// ---------------- final: mean, write ge; ic = ge@Wf2 + bf2; penalty ---------
__global__ void k_final(const float* __restrict__ gsum, const float* __restrict__ gcnt,
                        const float* __restrict__ Wf2, const float* __restrict__ bf2,
                        float* __restrict__ out) {
    __shared__ float ge[NG * DENSE];
    int tid = threadIdx.x;  // 128
    for (int idx = tid; idx < NG * DENSE; idx += 128) {
        int g = idx >> 7;
        float c = gcnt[g];
        float v = gsum[idx] / fmaxf(c, 1.0f);
        ge[idx] = v;
        out[idx] = v;
    }
    __syncthreads();
    if (tid < NG * LABELS) {
        int g = tid >> 1, l = tid & 1;
        float s = bf2[l];
#pragma unroll 8
        for (int c = 0; c < DENSE; c++)
            s += ge[g * DENSE + c] * Wf2[c * LABELS + l];
        out[NG * DENSE + 1 + tid] = s;
    }
    if (tid == 0) out[NG * DENSE] = 0.f;  // penalty
}

// ---------------- launch ----------------------------------------------------
extern "C" void kernel_launch(void* const* d_in, const int* in_sizes, int n_in,
                              void* d_out, int out_size) {
    const float* x   = (const float*)d_in[0];
    const float* W1  = (const float*)d_in[1];
    const float* b1  = (const float*)d_in[2];
    const float* W2  = (const float*)d_in[3];
    const float* b2  = (const float*)d_in[4];
    const float* Wf1 = (const float*)d_in[5];
    const float* bf1 = (const float*)d_in[6];
    const float* Wf2 = (const float*)d_in[7];
    const float* bf2 = (const float*)d_in[8];
    const int* ei    = (const int*)d_in[9];
    const int* batch = (const int*)d_in[10];
    const int* src = ei;
    const int* dst = ei + EE;
    float* out = (float*)d_out;

    float *dis, *h, *agg, *h1, *gsum, *gcnt;
    cudaGetSymbolAddress((void**)&dis,  g_dis);
    cudaGetSymbolAddress((void**)&h,    g_h);
    cudaGetSymbolAddress((void**)&agg,  g_agg);
    cudaGetSymbolAddress((void**)&h1,   g_h1);
    cudaGetSymbolAddress((void**)&gsum, g_gsum);
    cudaGetSymbolAddress((void**)&gcnt, g_gcnt);

    const int TB = 256;
    const int nblkN   = (NN + TB - 1) / TB;
    const int ew_grid = 148 * 16;                 // elementwise / scatter grid
    const int gemm_blocks = (NN + 63) / 64;

    // degree + normalization
    k_init_deg<<<nblkN, TB>>>(dis);
    k_deg_scatter<<<ew_grid, TB>>>(dst, dis);
    k_rsqrt<<<nblkN, TB>>>(dis);

    // ---- layer 1: h = x@W1 ; agg = sym-norm propagate ; h1 = relu(agg+b1)
    k_gemm<128, 128, false><<<gemm_blocks, 256>>>(x, W1, nullptr, h, NN);
    k_self_init<128><<<ew_grid, TB>>>(h, dis, agg);
    k_edge_scatter<128><<<ew_grid, TB>>>(h, dis, src, dst, agg);
    k_bias_relu<128><<<ew_grid, TB>>>(agg, b1, h1);

    // ---- layer 2: h = h1@W2 (64) ; propagate ; h2 = relu -> reuse g_h
    k_gemm<128, 64, false><<<gemm_blocks, 256>>>(h1, W2, nullptr, h, NN);
    k_self_init<64><<<ew_grid, TB>>>(h, dis, agg);
    k_edge_scatter<64><<<ew_grid, TB>>>(h, dis, src, dst, agg);
    k_bias_relu<64><<<ew_grid, TB>>>(agg, b2, h);

    // ---- dense: a1 = h2@Wf1 + bf1  -> g_h1
    k_gemm<64, 128, true><<<gemm_blocks, 256>>>(h, Wf1, bf1, h1, NN);

    // ---- pooling + head
    k_zero_pool<<<(NG * DENSE + TB - 1) / TB, TB>>>(gsum, gcnt);
    k_count<<<nblkN, TB>>>(batch, gcnt);
    k_pool<<<(NN + 255) / 256, 256>>>(h1, batch, gsum);
    k_final<<<1, 128>>>(gsum, gcnt, Wf2, bf2, out);
}

// round 2
// speedup vs baseline: 2.9627x; 2.9627x over previous
#include <cuda_runtime.h>
#include <cuda_bf16.h>

// Problem constants (fixed by the dataset)
#define NN 100000
#define EE 3200000
#define NG 64
#define F_IN 128
#define H1 128
#define H2 64
#define DENSE 128
#define LABELS 2

#define SCAN_BLK 512
#define NB_SCAN ((NN + SCAN_BLK - 1) / SCAN_BLK)   // 196

// ---------------- scratch (__device__ globals; no runtime allocation) -------
__device__ float g_dis[NN];
__device__ int   g_deg[NN];                 // edge in-degree (no self loop)
__device__ int   g_rowptr[NN];
__device__ int   g_nextptr[NN];
__device__ int   g_partials[256];
__device__ int   g_csr_src[EE];
__device__ float g_csr_w[EE];               // dis[src] per CSR slot
__device__ float g_h [(size_t)NN * 128];    // gemm outputs
__device__ float g_h1[(size_t)NN * 128];    // relu(layer1) / a1
__device__ float g_h2[(size_t)NN * 64];     // relu(layer2)
__device__ float g_gsum[NG * DENSE];
__device__ float g_gcnt[NG];

// ---------------- CSR build --------------------------------------------------
__global__ void k_zero_deg(int* deg) {
    int i = blockIdx.x * blockDim.x + threadIdx.x;
    if (i < NN) deg[i] = 0;
}

__global__ void k_deg_count(const int* __restrict__ dst, int* __restrict__ deg) {
    int i = blockIdx.x * blockDim.x + threadIdx.x;
    int stride = gridDim.x * blockDim.x;
    for (; i < EE; i += stride) atomicAdd(&deg[dst[i]], 1);
}

__global__ void k_dis(const int* __restrict__ deg, float* __restrict__ dis) {
    int i = blockIdx.x * blockDim.x + threadIdx.x;
    if (i < NN) dis[i] = rsqrtf(1.0f + (float)deg[i]);
}

// exclusive scan of deg -> rowptr (3-phase)
__global__ void k_scan_block(const int* __restrict__ deg, int* __restrict__ rowptr,
                             int* __restrict__ partials) {
    __shared__ int s[SCAN_BLK];
    int tid = threadIdx.x;
    int i = blockIdx.x * SCAN_BLK + tid;
    int v = (i < NN) ? deg[i] : 0;
    s[tid] = v;
    __syncthreads();
#pragma unroll
    for (int off = 1; off < SCAN_BLK; off <<= 1) {
        int t = (tid >= off) ? s[tid - off] : 0;
        __syncthreads();
        s[tid] += t;
        __syncthreads();
    }
    if (i < NN) rowptr[i] = s[tid] - v;           // exclusive
    if (tid == SCAN_BLK - 1) partials[blockIdx.x] = s[tid];
}

__global__ void k_scan_partials(int* __restrict__ partials) {
    __shared__ int s[256];
    int tid = threadIdx.x;
    int v = (tid < NB_SCAN) ? partials[tid] : 0;
    s[tid] = v;
    __syncthreads();
#pragma unroll
    for (int off = 1; off < 256; off <<= 1) {
        int t = (tid >= off) ? s[tid - off] : 0;
        __syncthreads();
        s[tid] += t;
        __syncthreads();
    }
    if (tid < NB_SCAN) partials[tid] = s[tid] - v; // exclusive
}

__global__ void k_scan_add(int* __restrict__ rowptr, const int* __restrict__ partials,
                           int* __restrict__ nextptr) {
    int i = blockIdx.x * blockDim.x + threadIdx.x;
    if (i < NN) {
        int r = rowptr[i] + partials[i / SCAN_BLK];
        rowptr[i] = r;
        nextptr[i] = r;
    }
}

__global__ void k_fill(const int* __restrict__ src, const int* __restrict__ dst,
                       const float* __restrict__ dis,
                       int* __restrict__ nextptr,
                       int* __restrict__ csr_src, float* __restrict__ csr_w) {
    int i = blockIdx.x * blockDim.x + threadIdx.x;
    int stride = gridDim.x * blockDim.x;
    for (; i < EE; i += stride) {
        int d = dst[i];
        int s = src[i];
        int pos = atomicAdd(&nextptr[d], 1);
        csr_src[pos] = s;
        csr_w[pos] = dis[s];
    }
}

// ---------------- fused gather: out = relu(dis[d]*sum + h[d]*dis[d]^2 + b) --
// K=128: warp per node, lane covers float4 (32*4 = 128 cols)
__global__ void __launch_bounds__(256)
k_gather128(const float* __restrict__ h, const float* __restrict__ dis,
            const int* __restrict__ deg, const int* __restrict__ rowptr,
            const int* __restrict__ csr_src, const float* __restrict__ csr_w,
            const float* __restrict__ bias, float* __restrict__ out) {
    int warp = (blockIdx.x * blockDim.x + threadIdx.x) >> 5;
    int lane = threadIdx.x & 31;
    int nwarps = (gridDim.x * blockDim.x) >> 5;
    for (int node = warp; node < NN; node += nwarps) {
        int beg = rowptr[node];
        int end = beg + deg[node];
        float4 acc0 = make_float4(0.f, 0.f, 0.f, 0.f);
        float4 acc1 = make_float4(0.f, 0.f, 0.f, 0.f);
        int e = beg;
        for (; e + 1 < end; e += 2) {
            int s0 = __ldg(&csr_src[e]);
            int s1 = __ldg(&csr_src[e + 1]);
            float w0 = __ldg(&csr_w[e]);
            float w1 = __ldg(&csr_w[e + 1]);
            float4 v0 = *(const float4*)(h + (size_t)s0 * 128 + lane * 4);
            float4 v1 = *(const float4*)(h + (size_t)s1 * 128 + lane * 4);
            acc0.x += v0.x * w0; acc0.y += v0.y * w0;
            acc0.z += v0.z * w0; acc0.w += v0.w * w0;
            acc1.x += v1.x * w1; acc1.y += v1.y * w1;
            acc1.z += v1.z * w1; acc1.w += v1.w * w1;
        }
        if (e < end) {
            int s0 = __ldg(&csr_src[e]);
            float w0 = __ldg(&csr_w[e]);
            float4 v0 = *(const float4*)(h + (size_t)s0 * 128 + lane * 4);
            acc0.x += v0.x * w0; acc0.y += v0.y * w0;
            acc0.z += v0.z * w0; acc0.w += v0.w * w0;
        }
        float dn = dis[node];
        float dn2 = dn * dn;
        float4 sv = *(const float4*)(h + (size_t)node * 128 + lane * 4);
        float4 bv = *(const float4*)(bias + lane * 4);
        float4 r;
        r.x = (acc0.x + acc1.x) * dn + sv.x * dn2 + bv.x;
        r.y = (acc0.y + acc1.y) * dn + sv.y * dn2 + bv.y;
        r.z = (acc0.z + acc1.z) * dn + sv.z * dn2 + bv.z;
        r.w = (acc0.w + acc1.w) * dn + sv.w * dn2 + bv.w;
        r.x = r.x > 0.f ? r.x : 0.f;
        r.y = r.y > 0.f ? r.y : 0.f;
        r.z = r.z > 0.f ? r.z : 0.f;
        r.w = r.w > 0.f ? r.w : 0.f;
        *(float4*)(out + (size_t)node * 128 + lane * 4) = r;
    }
}

// K=64: warp per node, lane covers float2 (32*2 = 64 cols)
__global__ void __launch_bounds__(256)
k_gather64(const float* __restrict__ h, const float* __restrict__ dis,
           const int* __restrict__ deg, const int* __restrict__ rowptr,
           const int* __restrict__ csr_src, const float* __restrict__ csr_w,
           const float* __restrict__ bias, float* __restrict__ out) {
    int warp = (blockIdx.x * blockDim.x + threadIdx.x) >> 5;
    int lane = threadIdx.x & 31;
    int nwarps = (gridDim.x * blockDim.x) >> 5;
    for (int node = warp; node < NN; node += nwarps) {
        int beg = rowptr[node];
        int end = beg + deg[node];
        float2 acc0 = make_float2(0.f, 0.f);
        float2 acc1 = make_float2(0.f, 0.f);
        int e = beg;
        for (; e + 1 < end; e += 2) {
            int s0 = __ldg(&csr_src[e]);
            int s1 = __ldg(&csr_src[e + 1]);
            float w0 = __ldg(&csr_w[e]);
            float w1 = __ldg(&csr_w[e + 1]);
            float2 v0 = *(const float2*)(h + (size_t)s0 * 64 + lane * 2);
            float2 v1 = *(const float2*)(h + (size_t)s1 * 64 + lane * 2);
            acc0.x += v0.x * w0; acc0.y += v0.y * w0;
            acc1.x += v1.x * w1; acc1.y += v1.y * w1;
        }
        if (e < end) {
            int s0 = __ldg(&csr_src[e]);
            float w0 = __ldg(&csr_w[e]);
            float2 v0 = *(const float2*)(h + (size_t)s0 * 64 + lane * 2);
            acc0.x += v0.x * w0; acc0.y += v0.y * w0;
        }
        float dn = dis[node];
        float dn2 = dn * dn;
        float2 sv = *(const float2*)(h + (size_t)node * 64 + lane * 2);
        float2 bv = *(const float2*)(bias + lane * 2);
        float2 r;
        r.x = (acc0.x + acc1.x) * dn + sv.x * dn2 + bv.x;
        r.y = (acc0.y + acc1.y) * dn + sv.y * dn2 + bv.y;
        r.x = r.x > 0.f ? r.x : 0.f;
        r.y = r.y > 0.f ? r.y : 0.f;
        *(float2*)(out + (size_t)node * 64 + lane * 2) = r;
    }
}

// ---------------- GEMM: C[M,NC] = A[M,K] @ B[K,NC] (+bias) -----------------
template<int K, int NC, bool BIAS>
__global__ void k_gemm(const float* __restrict__ A, const float* __restrict__ B,
                       const float* __restrict__ bias, float* __restrict__ C, int M) {
    constexpr int MT  = 64;
    constexpr int KC  = 32;
    constexpr int KP  = KC + 4;
    constexpr int CPT = NC / 16;
    __shared__ float sA[MT * KP];
    __shared__ float sB[KC * NC];

    int tid  = threadIdx.x;
    int row0 = blockIdx.x * MT;
    int rg = tid >> 4;
    int cg = tid & 15;
    int r0 = rg * 4;
    int c0 = cg * CPT;

    float acc[4][CPT];
#pragma unroll
    for (int i = 0; i < 4; i++)
#pragma unroll
        for (int j = 0; j < CPT; j++) acc[i][j] = 0.f;

    for (int kk = 0; kk < K; kk += KC) {
#pragma unroll
        for (int idx = tid * 4; idx < MT * KC; idx += 256 * 4) {
            int r = idx / KC, c = idx % KC;
            float4 v = make_float4(0.f, 0.f, 0.f, 0.f);
            if (row0 + r < M)
                v = *(const float4*)(A + (size_t)(row0 + r) * K + kk + c);
            *(float4*)(sA + r * KP + c) = v;
        }
#pragma unroll
        for (int idx = tid * 4; idx < KC * NC; idx += 256 * 4) {
            int r = idx / NC, c = idx % NC;
            *(float4*)(sB + idx) = *(const float4*)(B + (size_t)(kk + r) * NC + c);
        }
        __syncthreads();
#pragma unroll 4
        for (int k = 0; k < KC; k++) {
            float a[4];
#pragma unroll
            for (int i = 0; i < 4; i++) a[i] = sA[(r0 + i) * KP + k];
            float b[CPT];
#pragma unroll
            for (int j = 0; j < CPT; j += 4) {
                float4 bv = *(const float4*)(sB + k * NC + c0 + j);
                b[j] = bv.x; b[j + 1] = bv.y; b[j + 2] = bv.z; b[j + 3] = bv.w;
            }
#pragma unroll
            for (int i = 0; i < 4; i++)
#pragma unroll
                for (int j = 0; j < CPT; j++)
                    acc[i][j] += a[i] * b[j];
        }
        __syncthreads();
    }
#pragma unroll
    for (int i = 0; i < 4; i++) {
        int r = row0 + r0 + i;
        if (r < M) {
#pragma unroll
            for (int j = 0; j < CPT; j++) {
                float v = acc[i][j];
                if (BIAS) v += bias[c0 + j];
                C[(size_t)r * NC + c0 + j] = v;
            }
        }
    }
}

// ---------------- pooling ----------------------------------------------------
__global__ void k_zero_pool(float* gsum, float* gcnt) {
    int i = blockIdx.x * blockDim.x + threadIdx.x;
    if (i < NG * DENSE) gsum[i] = 0.f;
    if (i < NG) gcnt[i] = 0.f;
}

__global__ void k_count(const int* __restrict__ batch, float* __restrict__ gcnt) {
    int i = blockIdx.x * blockDim.x + threadIdx.x;
    unsigned act = __ballot_sync(0xffffffffu, i < NN);
    if (i < NN) {
        int b = batch[i];
        unsigned m = __match_any_sync(act, b);
        int leader = __ffs(m) - 1;
        if ((threadIdx.x & 31) == leader)
            atomicAdd(&gcnt[b], (float)__popc(m));
    }
}

__global__ void k_pool(const float* __restrict__ a1, const int* __restrict__ batch,
                       float* __restrict__ gsum) {
    constexpr int RB = 256;
    __shared__ float sm[4][DENSE];
    __shared__ int s_gmin, s_ngr;
    int base = blockIdx.x * RB;
    int nrows = NN - base; if (nrows > RB) nrows = RB;
    int tid = threadIdx.x;
    if (tid == 0) {
        int gmin = batch[base];
        int gmax = batch[base + nrows - 1];
        s_gmin = gmin; s_ngr = gmax - gmin + 1;
    }
    for (int i = tid; i < 4 * DENSE; i += 256) ((float*)sm)[i] = 0.f;
    __syncthreads();
    int gmin = s_gmin, ngr = s_ngr;
    int col = tid & 127, half = tid >> 7;
    if (ngr <= 4) {
        int curg = -1; float acc = 0.f;
        for (int r = half; r < nrows; r += 2) {
            int node = base + r;
            int g = batch[node];
            float v = a1[(size_t)node * DENSE + col];
            if (g != curg) {
                if (curg >= 0) atomicAdd(&sm[curg - gmin][col], acc);
                curg = g; acc = v;
            } else acc += v;
        }
        if (curg >= 0) atomicAdd(&sm[curg - gmin][col], acc);
        __syncthreads();
        if (tid < DENSE)
            for (int s = 0; s < ngr; s++)
                atomicAdd(&gsum[(size_t)(gmin + s) * DENSE + col], sm[s][col]);
    } else {
        for (int r = half; r < nrows; r += 2) {
            int node = base + r;
            atomicAdd(&gsum[(size_t)batch[node] * DENSE + col],
                      a1[(size_t)node * DENSE + col]);
        }
    }
}

__global__ void k_final(const float* __restrict__ gsum, const float* __restrict__ gcnt,
                        const float* __restrict__ Wf2, const float* __restrict__ bf2,
                        float* __restrict__ out) {
    __shared__ float ge[NG * DENSE];
    int tid = threadIdx.x;  // 128
    for (int idx = tid; idx < NG * DENSE; idx += 128) {
        int g = idx >> 7;
        float c = gcnt[g];
        float v = gsum[idx] / fmaxf(c, 1.0f);
        ge[idx] = v;
        out[idx] = v;
    }
    __syncthreads();
    if (tid < NG * LABELS) {
        int g = tid >> 1, l = tid & 1;
        float s = bf2[l];
#pragma unroll 8
        for (int c = 0; c < DENSE; c++)
            s += ge[g * DENSE + c] * Wf2[c * LABELS + l];
        out[NG * DENSE + 1 + tid] = s;
    }
    if (tid == 0) out[NG * DENSE] = 0.f;
}

// ---------------- launch ----------------------------------------------------
extern "C" void kernel_launch(void* const* d_in, const int* in_sizes, int n_in,
                              void* d_out, int out_size) {
    const float* x   = (const float*)d_in[0];
    const float* W1  = (const float*)d_in[1];
    const float* b1  = (const float*)d_in[2];
    const float* W2  = (const float*)d_in[3];
    const float* b2  = (const float*)d_in[4];
    const float* Wf1 = (const float*)d_in[5];
    const float* bf1 = (const float*)d_in[6];
    const float* Wf2 = (const float*)d_in[7];
    const float* bf2 = (const float*)d_in[8];
    const int* ei    = (const int*)d_in[9];
    const int* batch = (const int*)d_in[10];
    const int* src = ei;
    const int* dst = ei + EE;
    float* out = (float*)d_out;

    float *dis, *h, *h1, *h2, *gsum, *gcnt, *csr_w;
    int *deg, *rowptr, *nextptr, *partials, *csr_src;
    cudaGetSymbolAddress((void**)&dis,  g_dis);
    cudaGetSymbolAddress((void**)&deg,  g_deg);
    cudaGetSymbolAddress((void**)&rowptr, g_rowptr);
    cudaGetSymbolAddress((void**)&nextptr, g_nextptr);
    cudaGetSymbolAddress((void**)&partials, g_partials);
    cudaGetSymbolAddress((void**)&csr_src, g_csr_src);
    cudaGetSymbolAddress((void**)&csr_w, g_csr_w);
    cudaGetSymbolAddress((void**)&h,    g_h);
    cudaGetSymbolAddress((void**)&h1,   g_h1);
    cudaGetSymbolAddress((void**)&h2,   g_h2);
    cudaGetSymbolAddress((void**)&gsum, g_gsum);
    cudaGetSymbolAddress((void**)&gcnt, g_gcnt);

    const int TB = 256;
    const int nblkN = (NN + TB - 1) / TB;
    const int ew_grid = 148 * 16;
    const int gemm_blocks = (NN + 63) / 64;
    const int gather_blocks = (NN * 32 + TB - 1) / TB;  // warp per node

    // ---- CSR build + normalization
    k_zero_deg<<<nblkN, TB>>>(deg);
    k_deg_count<<<ew_grid, TB>>>(dst, deg);
    k_dis<<<nblkN, TB>>>(deg, dis);
    k_scan_block<<<NB_SCAN, SCAN_BLK>>>(deg, rowptr, partials);
    k_scan_partials<<<1, 256>>>(partials);
    k_scan_add<<<nblkN, TB>>>(rowptr, partials, nextptr);
    k_fill<<<ew_grid, TB>>>(src, dst, dis, nextptr, csr_src, csr_w);

    // ---- layer 1: h = x@W1 ; h1 = relu(propagate(h) + b1)   [fused]
    k_gemm<128, 128, false><<<gemm_blocks, 256>>>(x, W1, nullptr, h, NN);
    k_gather128<<<gather_blocks, TB>>>(h, dis, deg, rowptr, csr_src, csr_w, b1, h1);

    // ---- layer 2: h = h1@W2 ; h2 = relu(propagate(h) + b2)  [fused]
    k_gemm<128, 64, false><<<gemm_blocks, 256>>>(h1, W2, nullptr, h, NN);
    k_gather64<<<gather_blocks, TB>>>(h, dis, deg, rowptr, csr_src, csr_w, b2, h2);

    // ---- dense: a1 = h2@Wf1 + bf1  -> h1
    k_gemm<64, 128, true><<<gemm_blocks, 256>>>(h2, Wf1, bf1, h1, NN);

    // ---- pooling + head
    k_zero_pool<<<(NG * DENSE + TB - 1) / TB, TB>>>(gsum, gcnt);
    k_count<<<nblkN, TB>>>(batch, gcnt);
    k_pool<<<(NN + 255) / 256, 256>>>(h1, batch, gsum);
    k_final<<<1, 128>>>(gsum, gcnt, Wf2, bf2, out);
}

// round 3
// speedup vs baseline: 3.5173x; 1.1872x over previous
#include <cuda_runtime.h>
#include <cuda_bf16.h>
#include <cstdint>

// Problem constants (fixed by the dataset)
#define NN 100000
#define EE 3200000
#define NG 64
#define F_IN 128
#define H1 128
#define H2 64
#define DENSE 128
#define LABELS 2

#define SCAN_BLK 512
#define NB_SCAN ((NN + SCAN_BLK - 1) / SCAN_BLK)   // 196

// ---------------- scratch (__device__ globals; no runtime allocation) -------
__device__ float g_dis[NN];
__device__ int   g_deg[NN];
__device__ int   g_rowptr[NN];
__device__ int   g_nextptr[NN];
__device__ int   g_partials[256];
__device__ int   g_csr_src[EE];
__device__ float g_csr_w[EE];
__device__ float g_h [(size_t)NN * 128];    // gemm outputs
__device__ float g_h1[(size_t)NN * 128];    // relu(layer1)
__device__ float g_h2[(size_t)NN * 64];     // relu(layer2)
__device__ float g_gsum[NG * 64];
__device__ float g_gcnt[NG];

// ---------------- CSR build --------------------------------------------------
__global__ void k_zero_deg(int* deg) {
    int i = blockIdx.x * blockDim.x + threadIdx.x;
    if (i < NN) deg[i] = 0;
}

__global__ void k_deg_count(const int* __restrict__ dst, int* __restrict__ deg) {
    int i = blockIdx.x * blockDim.x + threadIdx.x;
    int stride = gridDim.x * blockDim.x;
    for (; i < EE; i += stride) atomicAdd(&deg[dst[i]], 1);
}

__global__ void k_dis(const int* __restrict__ deg, float* __restrict__ dis) {
    int i = blockIdx.x * blockDim.x + threadIdx.x;
    if (i < NN) dis[i] = rsqrtf(1.0f + (float)deg[i]);
}

__global__ void k_scan_block(const int* __restrict__ deg, int* __restrict__ rowptr,
                             int* __restrict__ partials) {
    __shared__ int s[SCAN_BLK];
    int tid = threadIdx.x;
    int i = blockIdx.x * SCAN_BLK + tid;
    int v = (i < NN) ? deg[i] : 0;
    s[tid] = v;
    __syncthreads();
#pragma unroll
    for (int off = 1; off < SCAN_BLK; off <<= 1) {
        int t = (tid >= off) ? s[tid - off] : 0;
        __syncthreads();
        s[tid] += t;
        __syncthreads();
    }
    if (i < NN) rowptr[i] = s[tid] - v;
    if (tid == SCAN_BLK - 1) partials[blockIdx.x] = s[tid];
}

__global__ void k_scan_partials(int* __restrict__ partials) {
    __shared__ int s[256];
    int tid = threadIdx.x;
    int v = (tid < NB_SCAN) ? partials[tid] : 0;
    s[tid] = v;
    __syncthreads();
#pragma unroll
    for (int off = 1; off < 256; off <<= 1) {
        int t = (tid >= off) ? s[tid - off] : 0;
        __syncthreads();
        s[tid] += t;
        __syncthreads();
    }
    if (tid < NB_SCAN) partials[tid] = s[tid] - v;
}

__global__ void k_scan_add(int* __restrict__ rowptr, const int* __restrict__ partials,
                           int* __restrict__ nextptr) {
    int i = blockIdx.x * blockDim.x + threadIdx.x;
    if (i < NN) {
        int r = rowptr[i] + partials[i / SCAN_BLK];
        rowptr[i] = r;
        nextptr[i] = r;
    }
}

__global__ void k_fill(const int* __restrict__ src, const int* __restrict__ dst,
                       const float* __restrict__ dis,
                       int* __restrict__ nextptr,
                       int* __restrict__ csr_src, float* __restrict__ csr_w) {
    int i = blockIdx.x * blockDim.x + threadIdx.x;
    int stride = gridDim.x * blockDim.x;
    for (; i < EE; i += stride) {
        int d = dst[i];
        int s = src[i];
        int pos = atomicAdd(&nextptr[d], 1);
        csr_src[pos] = s;
        csr_w[pos] = dis[s];
    }
}

// ---------------- tf32 helpers ----------------------------------------------
__device__ __forceinline__ uint32_t f2tf32(float f) {
    uint32_t r;
    asm("cvt.rna.tf32.f32 %0, %1;" : "=r"(r) : "f"(f));
    return r;
}

__device__ __forceinline__ void split_store4(float* hi, float* lo, float4 v) {
    uint32_t hx = f2tf32(v.x), hy = f2tf32(v.y), hz = f2tf32(v.z), hw = f2tf32(v.w);
    uint32_t lx = f2tf32(v.x - __uint_as_float(hx));
    uint32_t ly = f2tf32(v.y - __uint_as_float(hy));
    uint32_t lz = f2tf32(v.z - __uint_as_float(hz));
    uint32_t lw = f2tf32(v.w - __uint_as_float(hw));
    *(float4*)hi = make_float4(__uint_as_float(hx), __uint_as_float(hy),
                               __uint_as_float(hz), __uint_as_float(hw));
    *(float4*)lo = make_float4(__uint_as_float(lx), __uint_as_float(ly),
                               __uint_as_float(lz), __uint_as_float(lw));
}

__device__ __forceinline__ void mma_tf32(float d[4], const uint32_t a[4],
                                         uint32_t b0, uint32_t b1) {
    asm volatile(
        "mma.sync.aligned.m16n8k8.row.col.f32.tf32.tf32.f32 "
        "{%0,%1,%2,%3},{%4,%5,%6,%7},{%8,%9},{%0,%1,%2,%3};"
        : "+f"(d[0]), "+f"(d[1]), "+f"(d[2]), "+f"(d[3])
        : "r"(a[0]), "r"(a[1]), "r"(a[2]), "r"(a[3]), "r"(b0), "r"(b1));
}

// ---------------- tf32x3 GEMM: C[M,BN] = A[M,128] @ B[128,BN] ----------------
// BM=128, BK=16, 256 threads = 8 warps (4x2), warp tile 32 x (BN/2).
template<int BN>
__global__ void __launch_bounds__(256, 2)
k_gemm_tc(const float* __restrict__ A, const float* __restrict__ B,
          float* __restrict__ C, int M) {
    constexpr int BM = 128, BK = 16, KTOT = 128;
    constexpr int AP = 20;          // padded A row (floats)
    constexpr int BP = BN + 8;      // padded B row (floats)
    constexpr int NT = (BN / 2) / 8;// n-tiles per warp (8 or 4)
    __shared__ float sAh[BM * AP], sAl[BM * AP];
    __shared__ float sBh[BK * BP], sBl[BK * BP];

    int tid = threadIdx.x;
    int row0 = blockIdx.x * BM;
    int lane = tid & 31, warp = tid >> 5;
    int wr = warp >> 1, wc = warp & 1;
    int g = lane >> 2, tig = lane & 3;

    float acc[2][NT][4];
#pragma unroll
    for (int m = 0; m < 2; m++)
#pragma unroll
        for (int n = 0; n < NT; n++)
#pragma unroll
            for (int i = 0; i < 4; i++) acc[m][n][i] = 0.f;

    for (int kk = 0; kk < KTOT; kk += BK) {
        // load A tile [BM x BK] : 512 float4, 2 per thread
#pragma unroll
        for (int i = 0; i < 2; i++) {
            int j = tid + 256 * i;
            int r = j >> 2;
            int c4 = (j & 3) * 4;
            float4 v = make_float4(0.f, 0.f, 0.f, 0.f);
            if (row0 + r < M)
                v = *(const float4*)(A + (size_t)(row0 + r) * KTOT + kk + c4);
            split_store4(sAh + r * AP + c4, sAl + r * AP + c4, v);
        }
        // load B tile [BK x BN] : (BK*BN/4) float4
#pragma unroll
        for (int i = 0; i < BN / 64; i++) {
            int j = tid + 256 * i;
            int r = j / (BN / 4);
            int c4 = (j % (BN / 4)) * 4;
            float4 v = *(const float4*)(B + (size_t)(kk + r) * BN + c4);
            split_store4(sBh + r * BP + c4, sBl + r * BP + c4, v);
        }
        __syncthreads();

#pragma unroll
        for (int ks = 0; ks < 2; ks++) {
            int k0 = ks * 8;
            uint32_t ah[2][4], al[2][4];
#pragma unroll
            for (int mt = 0; mt < 2; mt++) {
                int rb = wr * 32 + mt * 16;
                ah[mt][0] = __float_as_uint(sAh[(rb + g) * AP + k0 + tig]);
                ah[mt][1] = __float_as_uint(sAh[(rb + g + 8) * AP + k0 + tig]);
                ah[mt][2] = __float_as_uint(sAh[(rb + g) * AP + k0 + tig + 4]);
                ah[mt][3] = __float_as_uint(sAh[(rb + g + 8) * AP + k0 + tig + 4]);
                al[mt][0] = __float_as_uint(sAl[(rb + g) * AP + k0 + tig]);
                al[mt][1] = __float_as_uint(sAl[(rb + g + 8) * AP + k0 + tig]);
                al[mt][2] = __float_as_uint(sAl[(rb + g) * AP + k0 + tig + 4]);
                al[mt][3] = __float_as_uint(sAl[(rb + g + 8) * AP + k0 + tig + 4]);
            }
#pragma unroll
            for (int nt = 0; nt < NT; nt++) {
                int nc = wc * (BN / 2) + nt * 8 + g;
                uint32_t bh0 = __float_as_uint(sBh[(k0 + tig) * BP + nc]);
                uint32_t bh1 = __float_as_uint(sBh[(k0 + tig + 4) * BP + nc]);
                uint32_t bl0 = __float_as_uint(sBl[(k0 + tig) * BP + nc]);
                uint32_t bl1 = __float_as_uint(sBl[(k0 + tig + 4) * BP + nc]);
#pragma unroll
                for (int mt = 0; mt < 2; mt++) {
                    mma_tf32(acc[mt][nt], al[mt], bh0, bh1);
                    mma_tf32(acc[mt][nt], ah[mt], bl0, bl1);
                    mma_tf32(acc[mt][nt], ah[mt], bh0, bh1);
                }
            }
        }
        __syncthreads();
    }

    // store
#pragma unroll
    for (int mt = 0; mt < 2; mt++) {
#pragma unroll
        for (int nt = 0; nt < NT; nt++) {
            int r1 = row0 + wr * 32 + mt * 16 + g;
            int r2 = r1 + 8;
            int cc = wc * (BN / 2) + nt * 8 + 2 * tig;
            if (r1 < M)
                *(float2*)(C + (size_t)r1 * BN + cc) =
                    make_float2(acc[mt][nt][0], acc[mt][nt][1]);
            if (r2 < M)
                *(float2*)(C + (size_t)r2 * BN + cc) =
                    make_float2(acc[mt][nt][2], acc[mt][nt][3]);
        }
    }
}

// ---------------- fused gather: out = relu(dis[d]*sum + h[d]*dis[d]^2 + b) --
__global__ void __launch_bounds__(256)
k_gather128(const float* __restrict__ h, const float* __restrict__ dis,
            const int* __restrict__ deg, const int* __restrict__ rowptr,
            const int* __restrict__ csr_src, const float* __restrict__ csr_w,
            const float* __restrict__ bias, float* __restrict__ out) {
    int warp = (blockIdx.x * blockDim.x + threadIdx.x) >> 5;
    int lane = threadIdx.x & 31;
    int nwarps = (gridDim.x * blockDim.x) >> 5;
    for (int node = warp; node < NN; node += nwarps) {
        int beg = rowptr[node];
        int end = beg + deg[node];
        float4 acc0 = make_float4(0.f, 0.f, 0.f, 0.f);
        float4 acc1 = make_float4(0.f, 0.f, 0.f, 0.f);
        int e = beg;
        for (; e + 1 < end; e += 2) {
            int s0 = __ldg(&csr_src[e]);
            int s1 = __ldg(&csr_src[e + 1]);
            float w0 = __ldg(&csr_w[e]);
            float w1 = __ldg(&csr_w[e + 1]);
            float4 v0 = *(const float4*)(h + (size_t)s0 * 128 + lane * 4);
            float4 v1 = *(const float4*)(h + (size_t)s1 * 128 + lane * 4);
            acc0.x += v0.x * w0; acc0.y += v0.y * w0;
            acc0.z += v0.z * w0; acc0.w += v0.w * w0;
            acc1.x += v1.x * w1; acc1.y += v1.y * w1;
            acc1.z += v1.z * w1; acc1.w += v1.w * w1;
        }
        if (e < end) {
            int s0 = __ldg(&csr_src[e]);
            float w0 = __ldg(&csr_w[e]);
            float4 v0 = *(const float4*)(h + (size_t)s0 * 128 + lane * 4);
            acc0.x += v0.x * w0; acc0.y += v0.y * w0;
            acc0.z += v0.z * w0; acc0.w += v0.w * w0;
        }
        float dn = dis[node];
        float dn2 = dn * dn;
        float4 sv = *(const float4*)(h + (size_t)node * 128 + lane * 4);
        float4 bv = *(const float4*)(bias + lane * 4);
        float4 r;
        r.x = (acc0.x + acc1.x) * dn + sv.x * dn2 + bv.x;
        r.y = (acc0.y + acc1.y) * dn + sv.y * dn2 + bv.y;
        r.z = (acc0.z + acc1.z) * dn + sv.z * dn2 + bv.z;
        r.w = (acc0.w + acc1.w) * dn + sv.w * dn2 + bv.w;
        r.x = r.x > 0.f ? r.x : 0.f;
        r.y = r.y > 0.f ? r.y : 0.f;
        r.z = r.z > 0.f ? r.z : 0.f;
        r.w = r.w > 0.f ? r.w : 0.f;
        *(float4*)(out + (size_t)node * 128 + lane * 4) = r;
    }
}

__global__ void __launch_bounds__(256)
k_gather64(const float* __restrict__ h, const float* __restrict__ dis,
           const int* __restrict__ deg, const int* __restrict__ rowptr,
           const int* __restrict__ csr_src, const float* __restrict__ csr_w,
           const float* __restrict__ bias, float* __restrict__ out) {
    int warp = (blockIdx.x * blockDim.x + threadIdx.x) >> 5;
    int lane = threadIdx.x & 31;
    int nwarps = (gridDim.x * blockDim.x) >> 5;
    for (int node = warp; node < NN; node += nwarps) {
        int beg = rowptr[node];
        int end = beg + deg[node];
        float2 acc0 = make_float2(0.f, 0.f);
        float2 acc1 = make_float2(0.f, 0.f);
        int e = beg;
        for (; e + 1 < end; e += 2) {
            int s0 = __ldg(&csr_src[e]);
            int s1 = __ldg(&csr_src[e + 1]);
            float w0 = __ldg(&csr_w[e]);
            float w1 = __ldg(&csr_w[e + 1]);
            float2 v0 = *(const float2*)(h + (size_t)s0 * 64 + lane * 2);
            float2 v1 = *(const float2*)(h + (size_t)s1 * 64 + lane * 2);
            acc0.x += v0.x * w0; acc0.y += v0.y * w0;
            acc1.x += v1.x * w1; acc1.y += v1.y * w1;
        }
        if (e < end) {
            int s0 = __ldg(&csr_src[e]);
            float w0 = __ldg(&csr_w[e]);
            float2 v0 = *(const float2*)(h + (size_t)s0 * 64 + lane * 2);
            acc0.x += v0.x * w0; acc0.y += v0.y * w0;
        }
        float dn = dis[node];
        float dn2 = dn * dn;
        float2 sv = *(const float2*)(h + (size_t)node * 64 + lane * 2);
        float2 bv = *(const float2*)(bias + lane * 2);
        float2 r;
        r.x = (acc0.x + acc1.x) * dn + sv.x * dn2 + bv.x;
        r.y = (acc0.y + acc1.y) * dn + sv.y * dn2 + bv.y;
        r.x = r.x > 0.f ? r.x : 0.f;
        r.y = r.y > 0.f ? r.y : 0.f;
        *(float2*)(out + (size_t)node * 64 + lane * 2) = r;
    }
}

// ---------------- pooling (64-wide, over h2) --------------------------------
__global__ void k_zero_pool(float* gsum, float* gcnt) {
    int i = blockIdx.x * blockDim.x + threadIdx.x;
    if (i < NG * 64) gsum[i] = 0.f;
    if (i < NG) gcnt[i] = 0.f;
}

__global__ void k_count(const int* __restrict__ batch, float* __restrict__ gcnt) {
    int i = blockIdx.x * blockDim.x + threadIdx.x;
    unsigned act = __ballot_sync(0xffffffffu, i < NN);
    if (i < NN) {
        int b = batch[i];
        unsigned m = __match_any_sync(act, b);
        int leader = __ffs(m) - 1;
        if ((threadIdx.x & 31) == leader)
            atomicAdd(&gcnt[b], (float)__popc(m));
    }
}

__global__ void k_pool64(const float* __restrict__ h2, const int* __restrict__ batch,
                         float* __restrict__ gsum) {
    constexpr int RB = 256;
    __shared__ float sm[4][64];
    __shared__ int s_gmin, s_ngr;
    int base = blockIdx.x * RB;
    int nrows = NN - base; if (nrows > RB) nrows = RB;
    int tid = threadIdx.x;
    if (tid == 0) {
        int gmin = batch[base];
        int gmax = batch[base + nrows - 1];
        s_gmin = gmin; s_ngr = gmax - gmin + 1;
    }
    for (int i = tid; i < 4 * 64; i += 256) ((float*)sm)[i] = 0.f;
    __syncthreads();
    int gmin = s_gmin, ngr = s_ngr;
    int col = tid & 63, strip = tid >> 6;       // 4 row-strips
    if (ngr <= 4) {
        int curg = -1; float acc = 0.f;
        for (int r = strip; r < nrows; r += 4) {
            int node = base + r;
            int g = batch[node];
            float v = h2[(size_t)node * 64 + col];
            if (g != curg) {
                if (curg >= 0) atomicAdd(&sm[curg - gmin][col], acc);
                curg = g; acc = v;
            } else acc += v;
        }
        if (curg >= 0) atomicAdd(&sm[curg - gmin][col], acc);
        __syncthreads();
        if (tid < 64)
            for (int s = 0; s < ngr; s++)
                atomicAdd(&gsum[(size_t)(gmin + s) * 64 + col], sm[s][col]);
    } else {
        for (int r = strip; r < nrows; r += 4) {
            int node = base + r;
            atomicAdd(&gsum[(size_t)batch[node] * 64 + col],
                      h2[(size_t)node * 64 + col]);
        }
    }
}

// ---------------- final: ge = (gsum/cnt)@Wf1+bf1 ; ic = ge@Wf2+bf2 ----------
__global__ void k_final2(const float* __restrict__ gsum, const float* __restrict__ gcnt,
                         const float* __restrict__ Wf1, const float* __restrict__ bf1,
                         const float* __restrict__ Wf2, const float* __restrict__ bf2,
                         float* __restrict__ out) {
    __shared__ float ge[NG * DENSE];           // 32 KB
    int tid = threadIdx.x;                     // 256
    for (int idx = tid; idx < NG * DENSE; idx += 256) {
        int gg = idx >> 7, j = idx & 127;
        float inv = 1.0f / fmaxf(gcnt[gg], 1.0f);
        const float* pg = gsum + gg * 64;
        float a = 0.f;
#pragma unroll 8
        for (int c = 0; c < 64; c++)
            a += pg[c] * Wf1[c * DENSE + j];
        float v = a * inv + bf1[j];
        ge[idx] = v;
        out[idx] = v;
    }
    __syncthreads();
    if (tid < NG * LABELS) {
        int gg = tid >> 1, l = tid & 1;
        float s = bf2[l];
#pragma unroll 8
        for (int c = 0; c < DENSE; c++)
            s += ge[gg * DENSE + c] * Wf2[c * LABELS + l];
        out[NG * DENSE + 1 + tid] = s;
    }
    if (tid == 0) out[NG * DENSE] = 0.f;       // penalty
}

// ---------------- launch ----------------------------------------------------
extern "C" void kernel_launch(void* const* d_in, const int* in_sizes, int n_in,
                              void* d_out, int out_size) {
    const float* x   = (const float*)d_in[0];
    const float* W1  = (const float*)d_in[1];
    const float* b1  = (const float*)d_in[2];
    const float* W2  = (const float*)d_in[3];
    const float* b2  = (const float*)d_in[4];
    const float* Wf1 = (const float*)d_in[5];
    const float* bf1 = (const float*)d_in[6];
    const float* Wf2 = (const float*)d_in[7];
    const float* bf2 = (const float*)d_in[8];
    const int* ei    = (const int*)d_in[9];
    const int* batch = (const int*)d_in[10];
    const int* src = ei;
    const int* dst = ei + EE;
    float* out = (float*)d_out;

    float *dis, *h, *h1, *h2, *gsum, *gcnt, *csr_w;
    int *deg, *rowptr, *nextptr, *partials, *csr_src;
    cudaGetSymbolAddress((void**)&dis,  g_dis);
    cudaGetSymbolAddress((void**)&deg,  g_deg);
    cudaGetSymbolAddress((void**)&rowptr, g_rowptr);
    cudaGetSymbolAddress((void**)&nextptr, g_nextptr);
    cudaGetSymbolAddress((void**)&partials, g_partials);
    cudaGetSymbolAddress((void**)&csr_src, g_csr_src);
    cudaGetSymbolAddress((void**)&csr_w, g_csr_w);
    cudaGetSymbolAddress((void**)&h,    g_h);
    cudaGetSymbolAddress((void**)&h1,   g_h1);
    cudaGetSymbolAddress((void**)&h2,   g_h2);
    cudaGetSymbolAddress((void**)&gsum, g_gsum);
    cudaGetSymbolAddress((void**)&gcnt, g_gcnt);

    const int TB = 256;
    const int nblkN = (NN + TB - 1) / TB;
    const int ew_grid = 148 * 16;
    const int gemm_blocks = (NN + 127) / 128;          // 782
    const int gather_blocks = (NN * 32 + TB - 1) / TB; // warp per node

    // ---- CSR build + normalization
    k_zero_deg<<<nblkN, TB>>>(deg);
    k_deg_count<<<ew_grid, TB>>>(dst, deg);
    k_dis<<<nblkN, TB>>>(deg, dis);
    k_scan_block<<<NB_SCAN, SCAN_BLK>>>(deg, rowptr, partials);
    k_scan_partials<<<1, 256>>>(partials);
    k_scan_add<<<nblkN, TB>>>(rowptr, partials, nextptr);
    k_fill<<<ew_grid, TB>>>(src, dst, dis, nextptr, csr_src, csr_w);

    // ---- layer 1: h = x@W1 (tf32x3 TC) ; h1 = relu(propagate(h)+b1)
    k_gemm_tc<128><<<gemm_blocks, 256>>>(x, W1, h, NN);
    k_gather128<<<gather_blocks, TB>>>(h, dis, deg, rowptr, csr_src, csr_w, b1, h1);

    // ---- layer 2: h = h1@W2 (tf32x3 TC) ; h2 = relu(propagate(h)+b2)
    k_gemm_tc<64><<<gemm_blocks, 256>>>(h1, W2, h, NN);
    k_gather64<<<gather_blocks, TB>>>(h, dis, deg, rowptr, csr_src, csr_w, b2, h2);

    // ---- pooling (Wf1 folded through the linear pooling) + head
    k_zero_pool<<<(NG * 64 + TB - 1) / TB, TB>>>(gsum, gcnt);
    k_count<<<nblkN, TB>>>(batch, gcnt);
    k_pool64<<<(NN + 255) / 256, 256>>>(h2, batch, gsum);
    k_final2<<<1, 256>>>(gsum, gcnt, Wf1, bf1, Wf2, bf2, out);
}

// round 4
// speedup vs baseline: 3.5243x; 1.0020x over previous
#include <cuda_runtime.h>
#include <cuda_bf16.h>
#include <cstdint>

// Problem constants (fixed by the dataset)
#define NN 100000
#define EE 3200000
#define NG 64
#define F_IN 128
#define H1 128
#define H2 64
#define DENSE 128
#define LABELS 2

#define SCAN_BLK 512
#define NB_SCAN ((NN + SCAN_BLK - 1) / SCAN_BLK)   // 196

// ---------------- scratch (__device__ globals; no runtime allocation) -------
__device__ float g_dis[NN];
__device__ int   g_deg[NN];
__device__ int   g_rowptr[NN];
__device__ int   g_nextptr[NN];
__device__ int   g_partials[256];
__device__ int2  g_csr[EE];                       // {src, float_bits(dis[src])}
__device__ __nv_bfloat16 g_hb[(size_t)NN * 128];  // gemm outputs (bf16)
__device__ float g_h1[(size_t)NN * 128];          // relu(layer1)
__device__ float g_h2[(size_t)NN * 64];           // relu(layer2)
__device__ float g_gsum[NG * 64];
__device__ float g_gcnt[NG];

// ---------------- CSR build --------------------------------------------------
__global__ void k_zero_deg(int* deg) {
    int i = blockIdx.x * blockDim.x + threadIdx.x;
    if (i < NN) deg[i] = 0;
}

__global__ void k_deg_count(const int* __restrict__ dst, int* __restrict__ deg) {
    int i = blockIdx.x * blockDim.x + threadIdx.x;
    int stride = gridDim.x * blockDim.x;
    for (; i < EE; i += stride) atomicAdd(&deg[dst[i]], 1);
}

__global__ void k_scan_block(const int* __restrict__ deg, int* __restrict__ rowptr,
                             int* __restrict__ partials) {
    __shared__ int s[SCAN_BLK];
    int tid = threadIdx.x;
    int i = blockIdx.x * SCAN_BLK + tid;
    int v = (i < NN) ? deg[i] : 0;
    s[tid] = v;
    __syncthreads();
#pragma unroll
    for (int off = 1; off < SCAN_BLK; off <<= 1) {
        int t = (tid >= off) ? s[tid - off] : 0;
        __syncthreads();
        s[tid] += t;
        __syncthreads();
    }
    if (i < NN) rowptr[i] = s[tid] - v;
    if (tid == SCAN_BLK - 1) partials[blockIdx.x] = s[tid];
}

__global__ void k_scan_partials(int* __restrict__ partials) {
    __shared__ int s[256];
    int tid = threadIdx.x;
    int v = (tid < NB_SCAN) ? partials[tid] : 0;
    s[tid] = v;
    __syncthreads();
#pragma unroll
    for (int off = 1; off < 256; off <<= 1) {
        int t = (tid >= off) ? s[tid - off] : 0;
        __syncthreads();
        s[tid] += t;
        __syncthreads();
    }
    if (tid < NB_SCAN) partials[tid] = s[tid] - v;
}

// fused: finalize rowptr, init nextptr, compute dis
__global__ void k_scan_add(int* __restrict__ rowptr, const int* __restrict__ partials,
                           int* __restrict__ nextptr, const int* __restrict__ deg,
                           float* __restrict__ dis) {
    int i = blockIdx.x * blockDim.x + threadIdx.x;
    if (i < NN) {
        int r = rowptr[i] + partials[i / SCAN_BLK];
        rowptr[i] = r;
        nextptr[i] = r;
        dis[i] = rsqrtf(1.0f + (float)deg[i]);
    }
}

__global__ void k_fill(const int* __restrict__ src, const int* __restrict__ dst,
                       const float* __restrict__ dis,
                       int* __restrict__ nextptr, int2* __restrict__ csr) {
    int i = blockIdx.x * blockDim.x + threadIdx.x;
    int stride = gridDim.x * blockDim.x;
    for (; i < EE; i += stride) {
        int d = dst[i];
        int s = src[i];
        int pos = atomicAdd(&nextptr[d], 1);
        csr[pos] = make_int2(s, __float_as_int(__ldg(&dis[s])));
    }
}

// ---------------- tf32 helpers ----------------------------------------------
__device__ __forceinline__ uint32_t f2tf32(float f) {
    uint32_t r;
    asm("cvt.rna.tf32.f32 %0, %1;" : "=r"(r) : "f"(f));
    return r;
}

__device__ __forceinline__ void split_store4(float* hi, float* lo, float4 v) {
    uint32_t hx = f2tf32(v.x), hy = f2tf32(v.y), hz = f2tf32(v.z), hw = f2tf32(v.w);
    uint32_t lx = f2tf32(v.x - __uint_as_float(hx));
    uint32_t ly = f2tf32(v.y - __uint_as_float(hy));
    uint32_t lz = f2tf32(v.z - __uint_as_float(hz));
    uint32_t lw = f2tf32(v.w - __uint_as_float(hw));
    *(float4*)hi = make_float4(__uint_as_float(hx), __uint_as_float(hy),
                               __uint_as_float(hz), __uint_as_float(hw));
    *(float4*)lo = make_float4(__uint_as_float(lx), __uint_as_float(ly),
                               __uint_as_float(lz), __uint_as_float(lw));
}

__device__ __forceinline__ void mma_tf32(float d[4], const uint32_t a[4],
                                         uint32_t b0, uint32_t b1) {
    asm volatile(
        "mma.sync.aligned.m16n8k8.row.col.f32.tf32.tf32.f32 "
        "{%0,%1,%2,%3},{%4,%5,%6,%7},{%8,%9},{%0,%1,%2,%3};"
        : "+f"(d[0]), "+f"(d[1]), "+f"(d[2]), "+f"(d[3])
        : "r"(a[0]), "r"(a[1]), "r"(a[2]), "r"(a[3]), "r"(b0), "r"(b1));
}

// ---------------- tf32x3 GEMM: Cb[M,BN] = bf16(A[M,128] @ B[128,BN]) --------
template<int BN>
__global__ void __launch_bounds__(256, 2)
k_gemm_tc(const float* __restrict__ A, const float* __restrict__ B,
          __nv_bfloat16* __restrict__ Cb, int M) {
    constexpr int BM = 128, BK = 16, KTOT = 128;
    constexpr int AP = 20;
    constexpr int BP = BN + 8;
    constexpr int NT = (BN / 2) / 8;
    __shared__ float sAh[BM * AP], sAl[BM * AP];
    __shared__ float sBh[BK * BP], sBl[BK * BP];

    int tid = threadIdx.x;
    int row0 = blockIdx.x * BM;
    int lane = tid & 31, warp = tid >> 5;
    int wr = warp >> 1, wc = warp & 1;
    int g = lane >> 2, tig = lane & 3;

    float acc[2][NT][4];
#pragma unroll
    for (int m = 0; m < 2; m++)
#pragma unroll
        for (int n = 0; n < NT; n++)
#pragma unroll
            for (int i = 0; i < 4; i++) acc[m][n][i] = 0.f;

    for (int kk = 0; kk < KTOT; kk += BK) {
#pragma unroll
        for (int i = 0; i < 2; i++) {
            int j = tid + 256 * i;
            int r = j >> 2;
            int c4 = (j & 3) * 4;
            float4 v = make_float4(0.f, 0.f, 0.f, 0.f);
            if (row0 + r < M)
                v = *(const float4*)(A + (size_t)(row0 + r) * KTOT + kk + c4);
            split_store4(sAh + r * AP + c4, sAl + r * AP + c4, v);
        }
#pragma unroll
        for (int i = 0; i < BN / 64; i++) {
            int j = tid + 256 * i;
            int r = j / (BN / 4);
            int c4 = (j % (BN / 4)) * 4;
            float4 v = *(const float4*)(B + (size_t)(kk + r) * BN + c4);
            split_store4(sBh + r * BP + c4, sBl + r * BP + c4, v);
        }
        __syncthreads();

#pragma unroll
        for (int ks = 0; ks < 2; ks++) {
            int k0 = ks * 8;
            uint32_t ah[2][4], al[2][4];
#pragma unroll
            for (int mt = 0; mt < 2; mt++) {
                int rb = wr * 32 + mt * 16;
                ah[mt][0] = __float_as_uint(sAh[(rb + g) * AP + k0 + tig]);
                ah[mt][1] = __float_as_uint(sAh[(rb + g + 8) * AP + k0 + tig]);
                ah[mt][2] = __float_as_uint(sAh[(rb + g) * AP + k0 + tig + 4]);
                ah[mt][3] = __float_as_uint(sAh[(rb + g + 8) * AP + k0 + tig + 4]);
                al[mt][0] = __float_as_uint(sAl[(rb + g) * AP + k0 + tig]);
                al[mt][1] = __float_as_uint(sAl[(rb + g + 8) * AP + k0 + tig]);
                al[mt][2] = __float_as_uint(sAl[(rb + g) * AP + k0 + tig + 4]);
                al[mt][3] = __float_as_uint(sAl[(rb + g + 8) * AP + k0 + tig + 4]);
            }
#pragma unroll
            for (int nt = 0; nt < NT; nt++) {
                int nc = wc * (BN / 2) + nt * 8 + g;
                uint32_t bh0 = __float_as_uint(sBh[(k0 + tig) * BP + nc]);
                uint32_t bh1 = __float_as_uint(sBh[(k0 + tig + 4) * BP + nc]);
                uint32_t bl0 = __float_as_uint(sBl[(k0 + tig) * BP + nc]);
                uint32_t bl1 = __float_as_uint(sBl[(k0 + tig + 4) * BP + nc]);
#pragma unroll
                for (int mt = 0; mt < 2; mt++) {
                    mma_tf32(acc[mt][nt], al[mt], bh0, bh1);
                    mma_tf32(acc[mt][nt], ah[mt], bl0, bl1);
                    mma_tf32(acc[mt][nt], ah[mt], bh0, bh1);
                }
            }
        }
        __syncthreads();
    }

#pragma unroll
    for (int mt = 0; mt < 2; mt++) {
#pragma unroll
        for (int nt = 0; nt < NT; nt++) {
            int r1 = row0 + wr * 32 + mt * 16 + g;
            int r2 = r1 + 8;
            int cc = wc * (BN / 2) + nt * 8 + 2 * tig;
            if (r1 < M)
                *(__nv_bfloat162*)(Cb + (size_t)r1 * BN + cc) =
                    __float22bfloat162_rn(make_float2(acc[mt][nt][0], acc[mt][nt][1]));
            if (r2 < M)
                *(__nv_bfloat162*)(Cb + (size_t)r2 * BN + cc) =
                    __float22bfloat162_rn(make_float2(acc[mt][nt][2], acc[mt][nt][3]));
        }
    }
}

// ---------------- fused gather (bf16 in): out = relu(dn*sum + self*dn^2 + b)
__device__ __forceinline__ float4 bf4_to_f4(uint2 v) {
    float2 lo = __bfloat1622float2(*reinterpret_cast<__nv_bfloat162*>(&v.x));
    float2 hi = __bfloat1622float2(*reinterpret_cast<__nv_bfloat162*>(&v.y));
    return make_float4(lo.x, lo.y, hi.x, hi.y);
}

__global__ void __launch_bounds__(256)
k_gather128h(const __nv_bfloat16* __restrict__ hb, const float* __restrict__ dis,
             const int* __restrict__ deg, const int* __restrict__ rowptr,
             const int2* __restrict__ csr, const float* __restrict__ bias,
             float* __restrict__ out) {
    int warp = (blockIdx.x * blockDim.x + threadIdx.x) >> 5;
    int lane = threadIdx.x & 31;
    int nwarps = (gridDim.x * blockDim.x) >> 5;
    for (int node = warp; node < NN; node += nwarps) {
        int beg = rowptr[node];
        int cnt = deg[node];
        float4 a0 = make_float4(0.f, 0.f, 0.f, 0.f);
        float4 a1 = make_float4(0.f, 0.f, 0.f, 0.f);
        float4 a2 = make_float4(0.f, 0.f, 0.f, 0.f);
        float4 a3 = make_float4(0.f, 0.f, 0.f, 0.f);
        int e = 0;
        for (; e + 3 < cnt; e += 4) {
            int2 c0 = __ldg(&csr[beg + e]);
            int2 c1 = __ldg(&csr[beg + e + 1]);
            int2 c2 = __ldg(&csr[beg + e + 2]);
            int2 c3 = __ldg(&csr[beg + e + 3]);
            uint2 v0 = *(const uint2*)(hb + (size_t)c0.x * 128 + lane * 4);
            uint2 v1 = *(const uint2*)(hb + (size_t)c1.x * 128 + lane * 4);
            uint2 v2 = *(const uint2*)(hb + (size_t)c2.x * 128 + lane * 4);
            uint2 v3 = *(const uint2*)(hb + (size_t)c3.x * 128 + lane * 4);
            float w0 = __int_as_float(c0.y), w1 = __int_as_float(c1.y);
            float w2 = __int_as_float(c2.y), w3 = __int_as_float(c3.y);
            float4 f0 = bf4_to_f4(v0), f1 = bf4_to_f4(v1);
            float4 f2 = bf4_to_f4(v2), f3 = bf4_to_f4(v3);
            a0.x += f0.x * w0; a0.y += f0.y * w0; a0.z += f0.z * w0; a0.w += f0.w * w0;
            a1.x += f1.x * w1; a1.y += f1.y * w1; a1.z += f1.z * w1; a1.w += f1.w * w1;
            a2.x += f2.x * w2; a2.y += f2.y * w2; a2.z += f2.z * w2; a2.w += f2.w * w2;
            a3.x += f3.x * w3; a3.y += f3.y * w3; a3.z += f3.z * w3; a3.w += f3.w * w3;
        }
        for (; e < cnt; e++) {
            int2 c0 = __ldg(&csr[beg + e]);
            uint2 v0 = *(const uint2*)(hb + (size_t)c0.x * 128 + lane * 4);
            float w0 = __int_as_float(c0.y);
            float4 f0 = bf4_to_f4(v0);
            a0.x += f0.x * w0; a0.y += f0.y * w0; a0.z += f0.z * w0; a0.w += f0.w * w0;
        }
        float dn = dis[node];
        float dn2 = dn * dn;
        uint2 sb = *(const uint2*)(hb + (size_t)node * 128 + lane * 4);
        float4 sv = bf4_to_f4(sb);
        float4 bv = *(const float4*)(bias + lane * 4);
        float4 r;
        r.x = (a0.x + a1.x + a2.x + a3.x) * dn + sv.x * dn2 + bv.x;
        r.y = (a0.y + a1.y + a2.y + a3.y) * dn + sv.y * dn2 + bv.y;
        r.z = (a0.z + a1.z + a2.z + a3.z) * dn + sv.z * dn2 + bv.z;
        r.w = (a0.w + a1.w + a2.w + a3.w) * dn + sv.w * dn2 + bv.w;
        r.x = r.x > 0.f ? r.x : 0.f;
        r.y = r.y > 0.f ? r.y : 0.f;
        r.z = r.z > 0.f ? r.z : 0.f;
        r.w = r.w > 0.f ? r.w : 0.f;
        *(float4*)(out + (size_t)node * 128 + lane * 4) = r;
    }
}

__global__ void __launch_bounds__(256)
k_gather64h(const __nv_bfloat16* __restrict__ hb, const float* __restrict__ dis,
            const int* __restrict__ deg, const int* __restrict__ rowptr,
            const int2* __restrict__ csr, const float* __restrict__ bias,
            float* __restrict__ out) {
    int warp = (blockIdx.x * blockDim.x + threadIdx.x) >> 5;
    int lane = threadIdx.x & 31;
    int nwarps = (gridDim.x * blockDim.x) >> 5;
    for (int node = warp; node < NN; node += nwarps) {
        int beg = rowptr[node];
        int cnt = deg[node];
        float2 a0 = make_float2(0.f, 0.f);
        float2 a1 = make_float2(0.f, 0.f);
        float2 a2 = make_float2(0.f, 0.f);
        float2 a3 = make_float2(0.f, 0.f);
        int e = 0;
        for (; e + 3 < cnt; e += 4) {
            int2 c0 = __ldg(&csr[beg + e]);
            int2 c1 = __ldg(&csr[beg + e + 1]);
            int2 c2 = __ldg(&csr[beg + e + 2]);
            int2 c3 = __ldg(&csr[beg + e + 3]);
            uint32_t v0 = *(const uint32_t*)(hb + (size_t)c0.x * 64 + lane * 2);
            uint32_t v1 = *(const uint32_t*)(hb + (size_t)c1.x * 64 + lane * 2);
            uint32_t v2 = *(const uint32_t*)(hb + (size_t)c2.x * 64 + lane * 2);
            uint32_t v3 = *(const uint32_t*)(hb + (size_t)c3.x * 64 + lane * 2);
            float2 f0 = __bfloat1622float2(*reinterpret_cast<__nv_bfloat162*>(&v0));
            float2 f1 = __bfloat1622float2(*reinterpret_cast<__nv_bfloat162*>(&v1));
            float2 f2 = __bfloat1622float2(*reinterpret_cast<__nv_bfloat162*>(&v2));
            float2 f3 = __bfloat1622float2(*reinterpret_cast<__nv_bfloat162*>(&v3));
            float w0 = __int_as_float(c0.y), w1 = __int_as_float(c1.y);
            float w2 = __int_as_float(c2.y), w3 = __int_as_float(c3.y);
            a0.x += f0.x * w0; a0.y += f0.y * w0;
            a1.x += f1.x * w1; a1.y += f1.y * w1;
            a2.x += f2.x * w2; a2.y += f2.y * w2;
            a3.x += f3.x * w3; a3.y += f3.y * w3;
        }
        for (; e < cnt; e++) {
            int2 c0 = __ldg(&csr[beg + e]);
            uint32_t v0 = *(const uint32_t*)(hb + (size_t)c0.x * 64 + lane * 2);
            float2 f0 = __bfloat1622float2(*reinterpret_cast<__nv_bfloat162*>(&v0));
            float w0 = __int_as_float(c0.y);
            a0.x += f0.x * w0; a0.y += f0.y * w0;
        }
        float dn = dis[node];
        float dn2 = dn * dn;
        uint32_t sb = *(const uint32_t*)(hb + (size_t)node * 64 + lane * 2);
        float2 sv = __bfloat1622float2(*reinterpret_cast<__nv_bfloat162*>(&sb));
        float2 bv = *(const float2*)(bias + lane * 2);
        float2 r;
        r.x = (a0.x + a1.x + a2.x + a3.x) * dn + sv.x * dn2 + bv.x;
        r.y = (a0.y + a1.y + a2.y + a3.y) * dn + sv.y * dn2 + bv.y;
        r.x = r.x > 0.f ? r.x : 0.f;
        r.y = r.y > 0.f ? r.y : 0.f;
        *(float2*)(out + (size_t)node * 64 + lane * 2) = r;
    }
}

// ---------------- pooling (64-wide, over h2) --------------------------------
__global__ void k_zero_pool(float* gsum, float* gcnt) {
    int i = blockIdx.x * blockDim.x + threadIdx.x;
    if (i < NG * 64) gsum[i] = 0.f;
    if (i < NG) gcnt[i] = 0.f;
}

__global__ void k_count(const int* __restrict__ batch, float* __restrict__ gcnt) {
    int i = blockIdx.x * blockDim.x + threadIdx.x;
    unsigned act = __ballot_sync(0xffffffffu, i < NN);
    if (i < NN) {
        int b = batch[i];
        unsigned m = __match_any_sync(act, b);
        int leader = __ffs(m) - 1;
        if ((threadIdx.x & 31) == leader)
            atomicAdd(&gcnt[b], (float)__popc(m));
    }
}

__global__ void k_pool64(const float* __restrict__ h2, const int* __restrict__ batch,
                         float* __restrict__ gsum) {
    constexpr int RB = 256;
    __shared__ float sm[4][64];
    __shared__ int s_gmin, s_ngr;
    int base = blockIdx.x * RB;
    int nrows = NN - base; if (nrows > RB) nrows = RB;
    int tid = threadIdx.x;
    if (tid == 0) {
        int gmin = batch[base];
        int gmax = batch[base + nrows - 1];
        s_gmin = gmin; s_ngr = gmax - gmin + 1;
    }
    for (int i = tid; i < 4 * 64; i += 256) ((float*)sm)[i] = 0.f;
    __syncthreads();
    int gmin = s_gmin, ngr = s_ngr;
    int col = tid & 63, strip = tid >> 6;
    if (ngr <= 4) {
        int curg = -1; float acc = 0.f;
        for (int r = strip; r < nrows; r += 4) {
            int node = base + r;
            int g = batch[node];
            float v = h2[(size_t)node * 64 + col];
            if (g != curg) {
                if (curg >= 0) atomicAdd(&sm[curg - gmin][col], acc);
                curg = g; acc = v;
            } else acc += v;
        }
        if (curg >= 0) atomicAdd(&sm[curg - gmin][col], acc);
        __syncthreads();
        if (tid < 64)
            for (int s = 0; s < ngr; s++)
                atomicAdd(&gsum[(size_t)(gmin + s) * 64 + col], sm[s][col]);
    } else {
        for (int r = strip; r < nrows; r += 4) {
            int node = base + r;
            atomicAdd(&gsum[(size_t)batch[node] * 64 + col],
                      h2[(size_t)node * 64 + col]);
        }
    }
}

// ---------------- final: ge = (gsum/cnt)@Wf1+bf1 ; ic = ge@Wf2+bf2 ----------
__global__ void k_final2(const float* __restrict__ gsum, const float* __restrict__ gcnt,
                         const float* __restrict__ Wf1, const float* __restrict__ bf1,
                         const float* __restrict__ Wf2, const float* __restrict__ bf2,
                         float* __restrict__ out) {
    __shared__ float ge[NG * DENSE];
    int tid = threadIdx.x;                     // 256
    for (int idx = tid; idx < NG * DENSE; idx += 256) {
        int gg = idx >> 7, j = idx & 127;
        float inv = 1.0f / fmaxf(gcnt[gg], 1.0f);
        const float* pg = gsum + gg * 64;
        float a = 0.f;
#pragma unroll 8
        for (int c = 0; c < 64; c++)
            a += pg[c] * Wf1[c * DENSE + j];
        float v = a * inv + bf1[j];
        ge[idx] = v;
        out[idx] = v;
    }
    __syncthreads();
    if (tid < NG * LABELS) {
        int gg = tid >> 1, l = tid & 1;
        float s = bf2[l];
#pragma unroll 8
        for (int c = 0; c < DENSE; c++)
            s += ge[gg * DENSE + c] * Wf2[c * LABELS + l];
        out[NG * DENSE + 1 + tid] = s;
    }
    if (tid == 0) out[NG * DENSE] = 0.f;
}

// ---------------- launch ----------------------------------------------------
extern "C" void kernel_launch(void* const* d_in, const int* in_sizes, int n_in,
                              void* d_out, int out_size) {
    const float* x   = (const float*)d_in[0];
    const float* W1  = (const float*)d_in[1];
    const float* b1  = (const float*)d_in[2];
    const float* W2  = (const float*)d_in[3];
    const float* b2  = (const float*)d_in[4];
    const float* Wf1 = (const float*)d_in[5];
    const float* bf1 = (const float*)d_in[6];
    const float* Wf2 = (const float*)d_in[7];
    const float* bf2 = (const float*)d_in[8];
    const int* ei    = (const int*)d_in[9];
    const int* batch = (const int*)d_in[10];
    const int* src = ei;
    const int* dst = ei + EE;
    float* out = (float*)d_out;

    float *dis, *h1, *h2, *gsum, *gcnt;
    __nv_bfloat16* hb;
    int *deg, *rowptr, *nextptr, *partials;
    int2* csr;
    cudaGetSymbolAddress((void**)&dis,  g_dis);
    cudaGetSymbolAddress((void**)&deg,  g_deg);
    cudaGetSymbolAddress((void**)&rowptr, g_rowptr);
    cudaGetSymbolAddress((void**)&nextptr, g_nextptr);
    cudaGetSymbolAddress((void**)&partials, g_partials);
    cudaGetSymbolAddress((void**)&csr,  g_csr);
    cudaGetSymbolAddress((void**)&hb,   g_hb);
    cudaGetSymbolAddress((void**)&h1,   g_h1);
    cudaGetSymbolAddress((void**)&h2,   g_h2);
    cudaGetSymbolAddress((void**)&gsum, g_gsum);
    cudaGetSymbolAddress((void**)&gcnt, g_gcnt);

    const int TB = 256;
    const int nblkN = (NN + TB - 1) / TB;
    const int ew_grid = 148 * 16;
    const int gemm_blocks = (NN + 127) / 128;
    const int gather_blocks = (NN * 32 + TB - 1) / TB;

    // ---- CSR build + normalization
    k_zero_deg<<<nblkN, TB>>>(deg);
    k_deg_count<<<ew_grid, TB>>>(dst, deg);
    k_scan_block<<<NB_SCAN, SCAN_BLK>>>(deg, rowptr, partials);
    k_scan_partials<<<1, 256>>>(partials);
    k_scan_add<<<nblkN, TB>>>(rowptr, partials, nextptr, deg, dis);
    k_fill<<<ew_grid, TB>>>(src, dst, dis, nextptr, csr);

    // ---- layer 1: hb = bf16(x@W1) ; h1 = relu(propagate(hb)+b1)
    k_gemm_tc<128><<<gemm_blocks, 256>>>(x, W1, hb, NN);
    k_gather128h<<<gather_blocks, TB>>>(hb, dis, deg, rowptr, csr, b1, h1);

    // ---- layer 2: hb = bf16(h1@W2) ; h2 = relu(propagate(hb)+b2)
    k_gemm_tc<64><<<gemm_blocks, 256>>>(h1, W2, hb, NN);
    k_gather64h<<<gather_blocks, TB>>>(hb, dis, deg, rowptr, csr, b2, h2);

    // ---- pooling (Wf1 folded) + head
    k_zero_pool<<<(NG * 64 + TB - 1) / TB, TB>>>(gsum, gcnt);
    k_count<<<nblkN, TB>>>(batch, gcnt);
    k_pool64<<<(NN + 255) / 256, 256>>>(h2, batch, gsum);
    k_final2<<<1, 256>>>(gsum, gcnt, Wf1, bf1, Wf2, bf2, out);
}

// round 5
// speedup vs baseline: 3.9310x; 1.1154x over previous
#include <cuda_runtime.h>
#include <cuda_bf16.h>
#include <cstdint>

// Problem constants (fixed by the dataset)
#define NN 100000
#define EE 3200000
#define NG 64
#define F_IN 128
#define H1 128
#define H2 64
#define DENSE 128
#define LABELS 2

#define SCAN_BLK 512
#define NB_SCAN ((NN + SCAN_BLK - 1) / SCAN_BLK)   // 196

// ---------------- scratch (__device__ globals; no runtime allocation) -------
__device__ float g_dis[NN];
__device__ int   g_deg[NN];
__device__ int   g_rowptr[NN];
__device__ int   g_nextptr[NN];
__device__ int   g_partials[256];
__device__ int2  g_csr[EE];                       // {src, float_bits(dis[src])}
__device__ __nv_bfloat16 g_hb[(size_t)NN * 128];  // gemm outputs (bf16)
__device__ float g_h1[(size_t)NN * 128];          // relu(layer1)
__device__ float g_h2[(size_t)NN * 64];           // relu(layer2)
__device__ float g_gsum[NG * 64];
__device__ float g_gcnt[NG];

// ---------------- CSR build --------------------------------------------------
__global__ void k_zero_deg(int* deg) {
    int i = blockIdx.x * blockDim.x + threadIdx.x;
    if (i < NN) deg[i] = 0;
}

__global__ void k_deg_count(const int* __restrict__ dst, int* __restrict__ deg) {
    int i = blockIdx.x * blockDim.x + threadIdx.x;
    int stride = gridDim.x * blockDim.x;
    for (; i < EE; i += stride) atomicAdd(&deg[dst[i]], 1);
}

__global__ void k_scan_block(const int* __restrict__ deg, int* __restrict__ rowptr,
                             int* __restrict__ partials) {
    __shared__ int s[SCAN_BLK];
    int tid = threadIdx.x;
    int i = blockIdx.x * SCAN_BLK + tid;
    int v = (i < NN) ? deg[i] : 0;
    s[tid] = v;
    __syncthreads();
#pragma unroll
    for (int off = 1; off < SCAN_BLK; off <<= 1) {
        int t = (tid >= off) ? s[tid - off] : 0;
        __syncthreads();
        s[tid] += t;
        __syncthreads();
    }
    if (i < NN) rowptr[i] = s[tid] - v;
    if (tid == SCAN_BLK - 1) partials[blockIdx.x] = s[tid];
}

__global__ void k_scan_partials(int* __restrict__ partials) {
    __shared__ int s[256];
    int tid = threadIdx.x;
    int v = (tid < NB_SCAN) ? partials[tid] : 0;
    s[tid] = v;
    __syncthreads();
#pragma unroll
    for (int off = 1; off < 256; off <<= 1) {
        int t = (tid >= off) ? s[tid - off] : 0;
        __syncthreads();
        s[tid] += t;
        __syncthreads();
    }
    if (tid < NB_SCAN) partials[tid] = s[tid] - v;
}

// fused: finalize rowptr, init nextptr, compute dis
__global__ void k_scan_add(int* __restrict__ rowptr, const int* __restrict__ partials,
                           int* __restrict__ nextptr, const int* __restrict__ deg,
                           float* __restrict__ dis) {
    int i = blockIdx.x * blockDim.x + threadIdx.x;
    if (i < NN) {
        int r = rowptr[i] + partials[i / SCAN_BLK];
        rowptr[i] = r;
        nextptr[i] = r;
        dis[i] = rsqrtf(1.0f + (float)deg[i]);
    }
}

__global__ void k_fill(const int* __restrict__ src, const int* __restrict__ dst,
                       const float* __restrict__ dis,
                       int* __restrict__ nextptr, int2* __restrict__ csr) {
    int i = blockIdx.x * blockDim.x + threadIdx.x;
    int stride = gridDim.x * blockDim.x;
    for (; i < EE; i += stride) {
        int d = dst[i];
        int s = src[i];
        int pos = atomicAdd(&nextptr[d], 1);
        csr[pos] = make_int2(s, __float_as_int(__ldg(&dis[s])));
    }
}

// ---------------- tf32 helpers ----------------------------------------------
__device__ __forceinline__ uint32_t f2tf32(float f) {
    uint32_t r;
    asm("cvt.rna.tf32.f32 %0, %1;" : "=r"(r) : "f"(f));
    return r;
}

__device__ __forceinline__ void tf32_store4(float* p, float4 v) {
    uint32_t hx = f2tf32(v.x), hy = f2tf32(v.y), hz = f2tf32(v.z), hw = f2tf32(v.w);
    *(float4*)p = make_float4(__uint_as_float(hx), __uint_as_float(hy),
                              __uint_as_float(hz), __uint_as_float(hw));
}

__device__ __forceinline__ void mma_tf32(float d[4], const uint32_t a[4],
                                         uint32_t b0, uint32_t b1) {
    asm volatile(
        "mma.sync.aligned.m16n8k8.row.col.f32.tf32.tf32.f32 "
        "{%0,%1,%2,%3},{%4,%5,%6,%7},{%8,%9},{%0,%1,%2,%3};"
        : "+f"(d[0]), "+f"(d[1]), "+f"(d[2]), "+f"(d[3])
        : "r"(a[0]), "r"(a[1]), "r"(a[2]), "r"(a[3]), "r"(b0), "r"(b1));
}

// ---------------- tf32 GEMM: Cb[M,BN] = bf16(A[M,128] @ B[128,BN]) ----------
// BM=128, BK=16, 256 threads = 8 warps (4x2), warp tile 32 x (BN/2).
template<int BN>
__global__ void __launch_bounds__(256)
k_gemm_tc(const float* __restrict__ A, const float* __restrict__ B,
          __nv_bfloat16* __restrict__ Cb, int M) {
    constexpr int BM = 128, BK = 16, KTOT = 128;
    constexpr int AP = 20;
    constexpr int BP = BN + 8;
    constexpr int NT = (BN / 2) / 8;
    __shared__ float sA[BM * AP];
    __shared__ float sB[BK * BP];

    int tid = threadIdx.x;
    int row0 = blockIdx.x * BM;
    int lane = tid & 31, warp = tid >> 5;
    int wr = warp >> 1, wc = warp & 1;
    int g = lane >> 2, tig = lane & 3;

    float acc[2][NT][4];
#pragma unroll
    for (int m = 0; m < 2; m++)
#pragma unroll
        for (int n = 0; n < NT; n++)
#pragma unroll
            for (int i = 0; i < 4; i++) acc[m][n][i] = 0.f;

    for (int kk = 0; kk < KTOT; kk += BK) {
#pragma unroll
        for (int i = 0; i < 2; i++) {
            int j = tid + 256 * i;
            int r = j >> 2;
            int c4 = (j & 3) * 4;
            float4 v = make_float4(0.f, 0.f, 0.f, 0.f);
            if (row0 + r < M)
                v = *(const float4*)(A + (size_t)(row0 + r) * KTOT + kk + c4);
            tf32_store4(sA + r * AP + c4, v);
        }
#pragma unroll
        for (int i = 0; i < BN / 64; i++) {
            int j = tid + 256 * i;
            int r = j / (BN / 4);
            int c4 = (j % (BN / 4)) * 4;
            float4 v = *(const float4*)(B + (size_t)(kk + r) * BN + c4);
            tf32_store4(sB + r * BP + c4, v);
        }
        __syncthreads();

#pragma unroll
        for (int ks = 0; ks < 2; ks++) {
            int k0 = ks * 8;
            uint32_t a[2][4];
#pragma unroll
            for (int mt = 0; mt < 2; mt++) {
                int rb = wr * 32 + mt * 16;
                a[mt][0] = __float_as_uint(sA[(rb + g) * AP + k0 + tig]);
                a[mt][1] = __float_as_uint(sA[(rb + g + 8) * AP + k0 + tig]);
                a[mt][2] = __float_as_uint(sA[(rb + g) * AP + k0 + tig + 4]);
                a[mt][3] = __float_as_uint(sA[(rb + g + 8) * AP + k0 + tig + 4]);
            }
#pragma unroll
            for (int nt = 0; nt < NT; nt++) {
                int nc = wc * (BN / 2) + nt * 8 + g;
                uint32_t b0 = __float_as_uint(sB[(k0 + tig) * BP + nc]);
                uint32_t b1 = __float_as_uint(sB[(k0 + tig + 4) * BP + nc]);
#pragma unroll
                for (int mt = 0; mt < 2; mt++)
                    mma_tf32(acc[mt][nt], a[mt], b0, b1);
            }
        }
        __syncthreads();
    }

#pragma unroll
    for (int mt = 0; mt < 2; mt++) {
#pragma unroll
        for (int nt = 0; nt < NT; nt++) {
            int r1 = row0 + wr * 32 + mt * 16 + g;
            int r2 = r1 + 8;
            int cc = wc * (BN / 2) + nt * 8 + 2 * tig;
            if (r1 < M)
                *(__nv_bfloat162*)(Cb + (size_t)r1 * BN + cc) =
                    __float22bfloat162_rn(make_float2(acc[mt][nt][0], acc[mt][nt][1]));
            if (r2 < M)
                *(__nv_bfloat162*)(Cb + (size_t)r2 * BN + cc) =
                    __float22bfloat162_rn(make_float2(acc[mt][nt][2], acc[mt][nt][3]));
        }
    }
}

// ---------------- fused gather (bf16 in): out = relu(dn*sum + self*dn^2 + b)
__device__ __forceinline__ float4 bf4_to_f4(uint2 v) {
    float2 lo = __bfloat1622float2(*reinterpret_cast<__nv_bfloat162*>(&v.x));
    float2 hi = __bfloat1622float2(*reinterpret_cast<__nv_bfloat162*>(&v.y));
    return make_float4(lo.x, lo.y, hi.x, hi.y);
}

__global__ void __launch_bounds__(256)
k_gather128h(const __nv_bfloat16* __restrict__ hb, const float* __restrict__ dis,
             const int* __restrict__ deg, const int* __restrict__ rowptr,
             const int2* __restrict__ csr, const float* __restrict__ bias,
             float* __restrict__ out) {
    int warp = (blockIdx.x * blockDim.x + threadIdx.x) >> 5;
    int lane = threadIdx.x & 31;
    int nwarps = (gridDim.x * blockDim.x) >> 5;
    for (int node = warp; node < NN; node += nwarps) {
        int beg = rowptr[node];
        int cnt = deg[node];
        float4 a0 = make_float4(0.f, 0.f, 0.f, 0.f);
        float4 a1 = make_float4(0.f, 0.f, 0.f, 0.f);
        float4 a2 = make_float4(0.f, 0.f, 0.f, 0.f);
        float4 a3 = make_float4(0.f, 0.f, 0.f, 0.f);
        int e = 0;
        for (; e + 3 < cnt; e += 4) {
            int2 c0 = __ldg(&csr[beg + e]);
            int2 c1 = __ldg(&csr[beg + e + 1]);
            int2 c2 = __ldg(&csr[beg + e + 2]);
            int2 c3 = __ldg(&csr[beg + e + 3]);
            uint2 v0 = *(const uint2*)(hb + (size_t)c0.x * 128 + lane * 4);
            uint2 v1 = *(const uint2*)(hb + (size_t)c1.x * 128 + lane * 4);
            uint2 v2 = *(const uint2*)(hb + (size_t)c2.x * 128 + lane * 4);
            uint2 v3 = *(const uint2*)(hb + (size_t)c3.x * 128 + lane * 4);
            float w0 = __int_as_float(c0.y), w1 = __int_as_float(c1.y);
            float w2 = __int_as_float(c2.y), w3 = __int_as_float(c3.y);
            float4 f0 = bf4_to_f4(v0), f1 = bf4_to_f4(v1);
            float4 f2 = bf4_to_f4(v2), f3 = bf4_to_f4(v3);
            a0.x += f0.x * w0; a0.y += f0.y * w0; a0.z += f0.z * w0; a0.w += f0.w * w0;
            a1.x += f1.x * w1; a1.y += f1.y * w1; a1.z += f1.z * w1; a1.w += f1.w * w1;
            a2.x += f2.x * w2; a2.y += f2.y * w2; a2.z += f2.z * w2; a2.w += f2.w * w2;
            a3.x += f3.x * w3; a3.y += f3.y * w3; a3.z += f3.z * w3; a3.w += f3.w * w3;
        }
        for (; e < cnt; e++) {
            int2 c0 = __ldg(&csr[beg + e]);
            uint2 v0 = *(const uint2*)(hb + (size_t)c0.x * 128 + lane * 4);
            float w0 = __int_as_float(c0.y);
            float4 f0 = bf4_to_f4(v0);
            a0.x += f0.x * w0; a0.y += f0.y * w0; a0.z += f0.z * w0; a0.w += f0.w * w0;
        }
        float dn = dis[node];
        float dn2 = dn * dn;
        uint2 sb = *(const uint2*)(hb + (size_t)node * 128 + lane * 4);
        float4 sv = bf4_to_f4(sb);
        float4 bv = *(const float4*)(bias + lane * 4);
        float4 r;
        r.x = (a0.x + a1.x + a2.x + a3.x) * dn + sv.x * dn2 + bv.x;
        r.y = (a0.y + a1.y + a2.y + a3.y) * dn + sv.y * dn2 + bv.y;
        r.z = (a0.z + a1.z + a2.z + a3.z) * dn + sv.z * dn2 + bv.z;
        r.w = (a0.w + a1.w + a2.w + a3.w) * dn + sv.w * dn2 + bv.w;
        r.x = r.x > 0.f ? r.x : 0.f;
        r.y = r.y > 0.f ? r.y : 0.f;
        r.z = r.z > 0.f ? r.z : 0.f;
        r.w = r.w > 0.f ? r.w : 0.f;
        *(float4*)(out + (size_t)node * 128 + lane * 4) = r;
    }
}

__global__ void __launch_bounds__(256)
k_gather64h(const __nv_bfloat16* __restrict__ hb, const float* __restrict__ dis,
            const int* __restrict__ deg, const int* __restrict__ rowptr,
            const int2* __restrict__ csr, const float* __restrict__ bias,
            float* __restrict__ out) {
    int warp = (blockIdx.x * blockDim.x + threadIdx.x) >> 5;
    int lane = threadIdx.x & 31;
    int nwarps = (gridDim.x * blockDim.x) >> 5;
    for (int node = warp; node < NN; node += nwarps) {
        int beg = rowptr[node];
        int cnt = deg[node];
        float2 a0 = make_float2(0.f, 0.f);
        float2 a1 = make_float2(0.f, 0.f);
        float2 a2 = make_float2(0.f, 0.f);
        float2 a3 = make_float2(0.f, 0.f);
        int e = 0;
        for (; e + 3 < cnt; e += 4) {
            int2 c0 = __ldg(&csr[beg + e]);
            int2 c1 = __ldg(&csr[beg + e + 1]);
            int2 c2 = __ldg(&csr[beg + e + 2]);
            int2 c3 = __ldg(&csr[beg + e + 3]);
            uint32_t v0 = *(const uint32_t*)(hb + (size_t)c0.x * 64 + lane * 2);
            uint32_t v1 = *(const uint32_t*)(hb + (size_t)c1.x * 64 + lane * 2);
            uint32_t v2 = *(const uint32_t*)(hb + (size_t)c2.x * 64 + lane * 2);
            uint32_t v3 = *(const uint32_t*)(hb + (size_t)c3.x * 64 + lane * 2);
            float2 f0 = __bfloat1622float2(*reinterpret_cast<__nv_bfloat162*>(&v0));
            float2 f1 = __bfloat1622float2(*reinterpret_cast<__nv_bfloat162*>(&v1));
            float2 f2 = __bfloat1622float2(*reinterpret_cast<__nv_bfloat162*>(&v2));
            float2 f3 = __bfloat1622float2(*reinterpret_cast<__nv_bfloat162*>(&v3));
            float w0 = __int_as_float(c0.y), w1 = __int_as_float(c1.y);
            float w2 = __int_as_float(c2.y), w3 = __int_as_float(c3.y);
            a0.x += f0.x * w0; a0.y += f0.y * w0;
            a1.x += f1.x * w1; a1.y += f1.y * w1;
            a2.x += f2.x * w2; a2.y += f2.y * w2;
            a3.x += f3.x * w3; a3.y += f3.y * w3;
        }
        for (; e < cnt; e++) {
            int2 c0 = __ldg(&csr[beg + e]);
            uint32_t v0 = *(const uint32_t*)(hb + (size_t)c0.x * 64 + lane * 2);
            float2 f0 = __bfloat1622float2(*reinterpret_cast<__nv_bfloat162*>(&v0));
            float w0 = __int_as_float(c0.y);
            a0.x += f0.x * w0; a0.y += f0.y * w0;
        }
        float dn = dis[node];
        float dn2 = dn * dn;
        uint32_t sb = *(const uint32_t*)(hb + (size_t)node * 64 + lane * 2);
        float2 sv = __bfloat1622float2(*reinterpret_cast<__nv_bfloat162*>(&sb));
        float2 bv = *(const float2*)(bias + lane * 2);
        float2 r;
        r.x = (a0.x + a1.x + a2.x + a3.x) * dn + sv.x * dn2 + bv.x;
        r.y = (a0.y + a1.y + a2.y + a3.y) * dn + sv.y * dn2 + bv.y;
        r.x = r.x > 0.f ? r.x : 0.f;
        r.y = r.y > 0.f ? r.y : 0.f;
        *(float2*)(out + (size_t)node * 64 + lane * 2) = r;
    }
}

// ---------------- pooling (64-wide, over h2) --------------------------------
__global__ void k_zero_pool(float* gsum, float* gcnt) {
    int i = blockIdx.x * blockDim.x + threadIdx.x;
    if (i < NG * 64) gsum[i] = 0.f;
    if (i < NG) gcnt[i] = 0.f;
}

__global__ void k_count(const int* __restrict__ batch, float* __restrict__ gcnt) {
    int i = blockIdx.x * blockDim.x + threadIdx.x;
    unsigned act = __ballot_sync(0xffffffffu, i < NN);
    if (i < NN) {
        int b = batch[i];
        unsigned m = __match_any_sync(act, b);
        int leader = __ffs(m) - 1;
        if ((threadIdx.x & 31) == leader)
            atomicAdd(&gcnt[b], (float)__popc(m));
    }
}

__global__ void k_pool64(const float* __restrict__ h2, const int* __restrict__ batch,
                         float* __restrict__ gsum) {
    constexpr int RB = 256;
    __shared__ float sm[4][64];
    __shared__ int s_gmin, s_ngr;
    int base = blockIdx.x * RB;
    int nrows = NN - base; if (nrows > RB) nrows = RB;
    int tid = threadIdx.x;
    if (tid == 0) {
        int gmin = batch[base];
        int gmax = batch[base + nrows - 1];
        s_gmin = gmin; s_ngr = gmax - gmin + 1;
    }
    for (int i = tid; i < 4 * 64; i += 256) ((float*)sm)[i] = 0.f;
    __syncthreads();
    int gmin = s_gmin, ngr = s_ngr;
    int col = tid & 63, strip = tid >> 6;
    if (ngr <= 4) {
        int curg = -1; float acc = 0.f;
        for (int r = strip; r < nrows; r += 4) {
            int node = base + r;
            int g = batch[node];
            float v = h2[(size_t)node * 64 + col];
            if (g != curg) {
                if (curg >= 0) atomicAdd(&sm[curg - gmin][col], acc);
                curg = g; acc = v;
            } else acc += v;
        }
        if (curg >= 0) atomicAdd(&sm[curg - gmin][col], acc);
        __syncthreads();
        if (tid < 64)
            for (int s = 0; s < ngr; s++)
                atomicAdd(&gsum[(size_t)(gmin + s) * 64 + col], sm[s][col]);
    } else {
        for (int r = strip; r < nrows; r += 4) {
            int node = base + r;
            atomicAdd(&gsum[(size_t)batch[node] * 64 + col],
                      h2[(size_t)node * 64 + col]);
        }
    }
}

// ---------------- final: ge = (gsum/cnt)@Wf1+bf1 ; ic = ge@Wf2+bf2 ----------
__global__ void k_final2(const float* __restrict__ gsum, const float* __restrict__ gcnt,
                         const float* __restrict__ Wf1, const float* __restrict__ bf1,
                         const float* __restrict__ Wf2, const float* __restrict__ bf2,
                         float* __restrict__ out) {
    __shared__ float ge[NG * DENSE];
    int tid = threadIdx.x;                     // 256
    for (int idx = tid; idx < NG * DENSE; idx += 256) {
        int gg = idx >> 7, j = idx & 127;
        float inv = 1.0f / fmaxf(gcnt[gg], 1.0f);
        const float* pg = gsum + gg * 64;
        float a = 0.f;
#pragma unroll 8
        for (int c = 0; c < 64; c++)
            a += pg[c] * Wf1[c * DENSE + j];
        float v = a * inv + bf1[j];
        ge[idx] = v;
        out[idx] = v;
    }
    __syncthreads();
    if (tid < NG * LABELS) {
        int gg = tid >> 1, l = tid & 1;
        float s = bf2[l];
#pragma unroll 8
        for (int c = 0; c < DENSE; c++)
            s += ge[gg * DENSE + c] * Wf2[c * LABELS + l];
        out[NG * DENSE + 1 + tid] = s;
    }
    if (tid == 0) out[NG * DENSE] = 0.f;
}

// ---------------- launch ----------------------------------------------------
extern "C" void kernel_launch(void* const* d_in, const int* in_sizes, int n_in,
                              void* d_out, int out_size) {
    const float* x   = (const float*)d_in[0];
    const float* W1  = (const float*)d_in[1];
    const float* b1  = (const float*)d_in[2];
    const float* W2  = (const float*)d_in[3];
    const float* b2  = (const float*)d_in[4];
    const float* Wf1 = (const float*)d_in[5];
    const float* bf1 = (const float*)d_in[6];
    const float* Wf2 = (const float*)d_in[7];
    const float* bf2 = (const float*)d_in[8];
    const int* ei    = (const int*)d_in[9];
    const int* batch = (const int*)d_in[10];
    const int* src = ei;
    const int* dst = ei + EE;
    float* out = (float*)d_out;

    float *dis, *h1, *h2, *gsum, *gcnt;
    __nv_bfloat16* hb;
    int *deg, *rowptr, *nextptr, *partials;
    int2* csr;
    cudaGetSymbolAddress((void**)&dis,  g_dis);
    cudaGetSymbolAddress((void**)&deg,  g_deg);
    cudaGetSymbolAddress((void**)&rowptr, g_rowptr);
    cudaGetSymbolAddress((void**)&nextptr, g_nextptr);
    cudaGetSymbolAddress((void**)&partials, g_partials);
    cudaGetSymbolAddress((void**)&csr,  g_csr);
    cudaGetSymbolAddress((void**)&hb,   g_hb);
    cudaGetSymbolAddress((void**)&h1,   g_h1);
    cudaGetSymbolAddress((void**)&h2,   g_h2);
    cudaGetSymbolAddress((void**)&gsum, g_gsum);
    cudaGetSymbolAddress((void**)&gcnt, g_gcnt);

    const int TB = 256;
    const int nblkN = (NN + TB - 1) / TB;
    const int ew_grid = 148 * 16;
    const int gemm_blocks = (NN + 127) / 128;
    const int gather_blocks = (NN * 32 + TB - 1) / TB;

    // ---- CSR build + normalization (gemm1 moved to launch index 3 so the
    //      profiler's fixed sample slot captures it)
    k_zero_deg<<<nblkN, TB>>>(deg);                                      // 0
    k_deg_count<<<ew_grid, TB>>>(dst, deg);                              // 1
    k_scan_block<<<NB_SCAN, SCAN_BLK>>>(deg, rowptr, partials);          // 2
    k_gemm_tc<128><<<gemm_blocks, 256>>>(x, W1, hb, NN);                 // 3 (indep)
    k_scan_partials<<<1, 256>>>(partials);                               // 4
    k_scan_add<<<nblkN, TB>>>(rowptr, partials, nextptr, deg, dis);      // 5
    k_fill<<<ew_grid, TB>>>(src, dst, dis, nextptr, csr);                // 6

    // ---- layer 1: h1 = relu(propagate(hb)+b1)
    k_gather128h<<<gather_blocks, TB>>>(hb, dis, deg, rowptr, csr, b1, h1);

    // ---- layer 2: hb = bf16(h1@W2) ; h2 = relu(propagate(hb)+b2)
    k_gemm_tc<64><<<gemm_blocks, 256>>>(h1, W2, hb, NN);
    k_gather64h<<<gather_blocks, TB>>>(hb, dis, deg, rowptr, csr, b2, h2);

    // ---- pooling (Wf1 folded) + head
    k_zero_pool<<<(NG * 64 + TB - 1) / TB, TB>>>(gsum, gcnt);
    k_count<<<nblkN, TB>>>(batch, gcnt);
    k_pool64<<<(NN + 255) / 256, 256>>>(h2, batch, gsum);
    k_final2<<<1, 256>>>(gsum, gcnt, Wf1, bf1, Wf2, bf2, out);
}

// round 6
// speedup vs baseline: 4.7396x; 1.2057x over previous
#include <cuda_runtime.h>
#include <cuda_bf16.h>
#include <cstdint>

// Problem constants (fixed by the dataset)
#define NN 100000
#define EE 3200000
#define NG 64
#define F_IN 128
#define H1 128
#define H2 64
#define DENSE 128
#define LABELS 2

#define SCAN_BLK 512
#define NB_SCAN ((NN + SCAN_BLK - 1) / SCAN_BLK)   // 196

// ---------------- scratch (__device__ globals; no runtime allocation) -------
__device__ float g_dis[NN];
__device__ int   g_deg[NN];
__device__ int   g_rowptr[NN];
__device__ int   g_nextptr[NN];
__device__ int   g_partials[256];
__device__ int   g_csr[EE];                       // src per CSR slot
__device__ __nv_bfloat16 g_hb[(size_t)NN * 128];  // gemm outputs, pre-scaled by dis
__device__ float g_h1[(size_t)NN * 128];          // relu(layer1)
__device__ float g_h2[(size_t)NN * 64];           // relu(layer2)
__device__ float g_gsum[NG * 64];
__device__ float g_gcnt[NG];

// ---------------- CSR build --------------------------------------------------
__global__ void k_zero_deg(int* deg) {
    int i = blockIdx.x * blockDim.x + threadIdx.x;
    if (i < NN) deg[i] = 0;
}

__global__ void k_deg_count(const int* __restrict__ dst, int* __restrict__ deg) {
    int i = blockIdx.x * blockDim.x + threadIdx.x;
    int stride = gridDim.x * blockDim.x;
    const int4* d4 = (const int4*)dst;
    for (; i < EE / 4; i += stride) {
        int4 v = __ldg(&d4[i]);
        atomicAdd(&deg[v.x], 1);
        atomicAdd(&deg[v.y], 1);
        atomicAdd(&deg[v.z], 1);
        atomicAdd(&deg[v.w], 1);
    }
}

__global__ void k_scan_block(const int* __restrict__ deg, int* __restrict__ rowptr,
                             int* __restrict__ partials) {
    __shared__ int s[SCAN_BLK];
    int tid = threadIdx.x;
    int i = blockIdx.x * SCAN_BLK + tid;
    int v = (i < NN) ? deg[i] : 0;
    s[tid] = v;
    __syncthreads();
#pragma unroll
    for (int off = 1; off < SCAN_BLK; off <<= 1) {
        int t = (tid >= off) ? s[tid - off] : 0;
        __syncthreads();
        s[tid] += t;
        __syncthreads();
    }
    if (i < NN) rowptr[i] = s[tid] - v;
    if (tid == SCAN_BLK - 1) partials[blockIdx.x] = s[tid];
}

__global__ void k_scan_partials(int* __restrict__ partials) {
    __shared__ int s[256];
    int tid = threadIdx.x;
    int v = (tid < NB_SCAN) ? partials[tid] : 0;
    s[tid] = v;
    __syncthreads();
#pragma unroll
    for (int off = 1; off < 256; off <<= 1) {
        int t = (tid >= off) ? s[tid - off] : 0;
        __syncthreads();
        s[tid] += t;
        __syncthreads();
    }
    if (tid < NB_SCAN) partials[tid] = s[tid] - v;
}

// fused: finalize rowptr, init nextptr, compute dis
__global__ void k_scan_add(int* __restrict__ rowptr, const int* __restrict__ partials,
                           int* __restrict__ nextptr, const int* __restrict__ deg,
                           float* __restrict__ dis) {
    int i = blockIdx.x * blockDim.x + threadIdx.x;
    if (i < NN) {
        int r = rowptr[i] + partials[i / SCAN_BLK];
        rowptr[i] = r;
        nextptr[i] = r;
        dis[i] = rsqrtf(1.0f + (float)deg[i]);
    }
}

__global__ void k_fill(const int* __restrict__ src, const int* __restrict__ dst,
                       int* __restrict__ nextptr, int* __restrict__ csr) {
    int i = blockIdx.x * blockDim.x + threadIdx.x;
    int stride = gridDim.x * blockDim.x;
    for (; i < EE; i += stride) {
        int d = dst[i];
        int s = src[i];
        int pos = atomicAdd(&nextptr[d], 1);
        csr[pos] = s;
    }
}

// ---------------- tf32 helpers ----------------------------------------------
__device__ __forceinline__ uint32_t f2tf32(float f) {
    uint32_t r;
    asm("cvt.rna.tf32.f32 %0, %1;" : "=r"(r) : "f"(f));
    return r;
}

__device__ __forceinline__ void tf32_store4(float* p, float4 v) {
    uint32_t hx = f2tf32(v.x), hy = f2tf32(v.y), hz = f2tf32(v.z), hw = f2tf32(v.w);
    *(float4*)p = make_float4(__uint_as_float(hx), __uint_as_float(hy),
                              __uint_as_float(hz), __uint_as_float(hw));
}

__device__ __forceinline__ void mma_tf32(float d[4], const uint32_t a[4],
                                         uint32_t b0, uint32_t b1) {
    asm volatile(
        "mma.sync.aligned.m16n8k8.row.col.f32.tf32.tf32.f32 "
        "{%0,%1,%2,%3},{%4,%5,%6,%7},{%8,%9},{%0,%1,%2,%3};"
        : "+f"(d[0]), "+f"(d[1]), "+f"(d[2]), "+f"(d[3])
        : "r"(a[0]), "r"(a[1]), "r"(a[2]), "r"(a[3]), "r"(b0), "r"(b1));
}

// ---------------- tf32 GEMM: Cb[M,BN] = bf16((A[M,128] @ B[128,BN]) * dis[m])
template<int BN>
__global__ void __launch_bounds__(256)
k_gemm_tc(const float* __restrict__ A, const float* __restrict__ B,
          const float* __restrict__ dis, __nv_bfloat16* __restrict__ Cb, int M) {
    constexpr int BM = 128, BK = 16, KTOT = 128;
    constexpr int AP = 20;
    constexpr int BP = BN + 8;
    constexpr int NT = (BN / 2) / 8;
    __shared__ float sA[BM * AP];
    __shared__ float sB[BK * BP];

    int tid = threadIdx.x;
    int row0 = blockIdx.x * BM;
    int lane = tid & 31, warp = tid >> 5;
    int wr = warp >> 1, wc = warp & 1;
    int g = lane >> 2, tig = lane & 3;

    float acc[2][NT][4];
#pragma unroll
    for (int m = 0; m < 2; m++)
#pragma unroll
        for (int n = 0; n < NT; n++)
#pragma unroll
            for (int i = 0; i < 4; i++) acc[m][n][i] = 0.f;

    for (int kk = 0; kk < KTOT; kk += BK) {
#pragma unroll
        for (int i = 0; i < 2; i++) {
            int j = tid + 256 * i;
            int r = j >> 2;
            int c4 = (j & 3) * 4;
            float4 v = make_float4(0.f, 0.f, 0.f, 0.f);
            if (row0 + r < M)
                v = *(const float4*)(A + (size_t)(row0 + r) * KTOT + kk + c4);
            tf32_store4(sA + r * AP + c4, v);
        }
#pragma unroll
        for (int i = 0; i < BN / 64; i++) {
            int j = tid + 256 * i;
            int r = j / (BN / 4);
            int c4 = (j % (BN / 4)) * 4;
            float4 v = *(const float4*)(B + (size_t)(kk + r) * BN + c4);
            tf32_store4(sB + r * BP + c4, v);
        }
        __syncthreads();

#pragma unroll
        for (int ks = 0; ks < 2; ks++) {
            int k0 = ks * 8;
            uint32_t a[2][4];
#pragma unroll
            for (int mt = 0; mt < 2; mt++) {
                int rb = wr * 32 + mt * 16;
                a[mt][0] = __float_as_uint(sA[(rb + g) * AP + k0 + tig]);
                a[mt][1] = __float_as_uint(sA[(rb + g + 8) * AP + k0 + tig]);
                a[mt][2] = __float_as_uint(sA[(rb + g) * AP + k0 + tig + 4]);
                a[mt][3] = __float_as_uint(sA[(rb + g + 8) * AP + k0 + tig + 4]);
            }
#pragma unroll
            for (int nt = 0; nt < NT; nt++) {
                int nc = wc * (BN / 2) + nt * 8 + g;
                uint32_t b0 = __float_as_uint(sB[(k0 + tig) * BP + nc]);
                uint32_t b1 = __float_as_uint(sB[(k0 + tig + 4) * BP + nc]);
#pragma unroll
                for (int mt = 0; mt < 2; mt++)
                    mma_tf32(acc[mt][nt], a[mt], b0, b1);
            }
        }
        __syncthreads();
    }

#pragma unroll
    for (int mt = 0; mt < 2; mt++) {
        int r1 = row0 + wr * 32 + mt * 16 + g;
        int r2 = r1 + 8;
        float d1 = (r1 < M) ? __ldg(&dis[r1]) : 0.f;
        float d2 = (r2 < M) ? __ldg(&dis[r2]) : 0.f;
#pragma unroll
        for (int nt = 0; nt < NT; nt++) {
            int cc = wc * (BN / 2) + nt * 8 + 2 * tig;
            if (r1 < M)
                *(__nv_bfloat162*)(Cb + (size_t)r1 * BN + cc) =
                    __float22bfloat162_rn(make_float2(acc[mt][nt][0] * d1,
                                                      acc[mt][nt][1] * d1));
            if (r2 < M)
                *(__nv_bfloat162*)(Cb + (size_t)r2 * BN + cc) =
                    __float22bfloat162_rn(make_float2(acc[mt][nt][2] * d2,
                                                      acc[mt][nt][3] * d2));
        }
    }
}

// ---------------- fused gather: out = relu(dn*(sum_src hb + hb[node]) + b) --
// hb rows are pre-scaled by dis. Two edges per load instruction: half-warp
// (16 lanes) covers one row; lanes 16-31 cover the next edge's row.
__device__ __forceinline__ void accum8(float* a, uint4 v) {
    float2 f;
    f = __bfloat1622float2(*reinterpret_cast<__nv_bfloat162*>(&v.x));
    a[0] += f.x; a[1] += f.y;
    f = __bfloat1622float2(*reinterpret_cast<__nv_bfloat162*>(&v.y));
    a[2] += f.x; a[3] += f.y;
    f = __bfloat1622float2(*reinterpret_cast<__nv_bfloat162*>(&v.z));
    a[4] += f.x; a[5] += f.y;
    f = __bfloat1622float2(*reinterpret_cast<__nv_bfloat162*>(&v.w));
    a[6] += f.x; a[7] += f.y;
}

__device__ __forceinline__ void accum4(float* a, uint2 v) {
    float2 f;
    f = __bfloat1622float2(*reinterpret_cast<__nv_bfloat162*>(&v.x));
    a[0] += f.x; a[1] += f.y;
    f = __bfloat1622float2(*reinterpret_cast<__nv_bfloat162*>(&v.y));
    a[2] += f.x; a[3] += f.y;
}

__global__ void __launch_bounds__(256)
k_gather128s(const __nv_bfloat16* __restrict__ hb, const float* __restrict__ dis,
             const int* __restrict__ deg, const int* __restrict__ rowptr,
             const int* __restrict__ csr, const float* __restrict__ bias,
             float* __restrict__ out) {
    int warp = (blockIdx.x * blockDim.x + threadIdx.x) >> 5;
    int lane = threadIdx.x & 31;
    int h = lane >> 4;          // half id: handles edges e+h
    int l = lane & 15;          // 8 cols per lane
    int nwarps = (gridDim.x * blockDim.x) >> 5;
    for (int node = warp; node < NN; node += nwarps) {
        int beg = rowptr[node];
        int cnt = deg[node];
        float acc[8] = {0.f, 0.f, 0.f, 0.f, 0.f, 0.f, 0.f, 0.f};
        int off = beg + h;
        int e = 0;
        for (; e + 7 < cnt; e += 8) {
            int s0 = __ldg(csr + off + e);
            int s1 = __ldg(csr + off + e + 2);
            int s2 = __ldg(csr + off + e + 4);
            int s3 = __ldg(csr + off + e + 6);
            uint4 v0 = *(const uint4*)(hb + (size_t)s0 * 128 + l * 8);
            uint4 v1 = *(const uint4*)(hb + (size_t)s1 * 128 + l * 8);
            uint4 v2 = *(const uint4*)(hb + (size_t)s2 * 128 + l * 8);
            uint4 v3 = *(const uint4*)(hb + (size_t)s3 * 128 + l * 8);
            accum8(acc, v0); accum8(acc, v1); accum8(acc, v2); accum8(acc, v3);
        }
        for (; e < cnt; e += 2) {
            int idx = e + h;
            if (idx < cnt) {
                int s = __ldg(csr + beg + idx);
                uint4 v = *(const uint4*)(hb + (size_t)s * 128 + l * 8);
                accum8(acc, v);
            }
        }
        if (h == 0) {   // self term (hb already scaled by dis)
            uint4 v = *(const uint4*)(hb + (size_t)node * 128 + l * 8);
            accum8(acc, v);
        }
#pragma unroll
        for (int i = 0; i < 8; i++)
            acc[i] += __shfl_xor_sync(0xffffffffu, acc[i], 16);
        if (h == 0) {
            float dn = dis[node];
            float4 b0 = *(const float4*)(bias + l * 8);
            float4 b1 = *(const float4*)(bias + l * 8 + 4);
            float4 r0, r1;
            r0.x = fmaxf(acc[0] * dn + b0.x, 0.f);
            r0.y = fmaxf(acc[1] * dn + b0.y, 0.f);
            r0.z = fmaxf(acc[2] * dn + b0.z, 0.f);
            r0.w = fmaxf(acc[3] * dn + b0.w, 0.f);
            r1.x = fmaxf(acc[4] * dn + b1.x, 0.f);
            r1.y = fmaxf(acc[5] * dn + b1.y, 0.f);
            r1.z = fmaxf(acc[6] * dn + b1.z, 0.f);
            r1.w = fmaxf(acc[7] * dn + b1.w, 0.f);
            *(float4*)(out + (size_t)node * 128 + l * 8) = r0;
            *(float4*)(out + (size_t)node * 128 + l * 8 + 4) = r1;
        }
    }
}

__global__ void __launch_bounds__(256)
k_gather64s(const __nv_bfloat16* __restrict__ hb, const float* __restrict__ dis,
            const int* __restrict__ deg, const int* __restrict__ rowptr,
            const int* __restrict__ csr, const float* __restrict__ bias,
            float* __restrict__ out) {
    int warp = (blockIdx.x * blockDim.x + threadIdx.x) >> 5;
    int lane = threadIdx.x & 31;
    int h = lane >> 4;
    int l = lane & 15;          // 4 cols per lane
    int nwarps = (gridDim.x * blockDim.x) >> 5;
    for (int node = warp; node < NN; node += nwarps) {
        int beg = rowptr[node];
        int cnt = deg[node];
        float acc[4] = {0.f, 0.f, 0.f, 0.f};
        int off = beg + h;
        int e = 0;
        for (; e + 7 < cnt; e += 8) {
            int s0 = __ldg(csr + off + e);
            int s1 = __ldg(csr + off + e + 2);
            int s2 = __ldg(csr + off + e + 4);
            int s3 = __ldg(csr + off + e + 6);
            uint2 v0 = *(const uint2*)(hb + (size_t)s0 * 64 + l * 4);
            uint2 v1 = *(const uint2*)(hb + (size_t)s1 * 64 + l * 4);
            uint2 v2 = *(const uint2*)(hb + (size_t)s2 * 64 + l * 4);
            uint2 v3 = *(const uint2*)(hb + (size_t)s3 * 64 + l * 4);
            accum4(acc, v0); accum4(acc, v1); accum4(acc, v2); accum4(acc, v3);
        }
        for (; e < cnt; e += 2) {
            int idx = e + h;
            if (idx < cnt) {
                int s = __ldg(csr + beg + idx);
                uint2 v = *(const uint2*)(hb + (size_t)s * 64 + l * 4);
                accum4(acc, v);
            }
        }
        if (h == 0) {
            uint2 v = *(const uint2*)(hb + (size_t)node * 64 + l * 4);
            accum4(acc, v);
        }
#pragma unroll
        for (int i = 0; i < 4; i++)
            acc[i] += __shfl_xor_sync(0xffffffffu, acc[i], 16);
        if (h == 0) {
            float dn = dis[node];
            float4 bv = *(const float4*)(bias + l * 4);
            float4 r;
            r.x = fmaxf(acc[0] * dn + bv.x, 0.f);
            r.y = fmaxf(acc[1] * dn + bv.y, 0.f);
            r.z = fmaxf(acc[2] * dn + bv.z, 0.f);
            r.w = fmaxf(acc[3] * dn + bv.w, 0.f);
            *(float4*)(out + (size_t)node * 64 + l * 4) = r;
        }
    }
}

// ---------------- pooling (64-wide, over h2) --------------------------------
__global__ void k_zero_pool(float* gsum, float* gcnt) {
    int i = blockIdx.x * blockDim.x + threadIdx.x;
    if (i < NG * 64) gsum[i] = 0.f;
    if (i < NG) gcnt[i] = 0.f;
}

__global__ void k_count(const int* __restrict__ batch, float* __restrict__ gcnt) {
    int i = blockIdx.x * blockDim.x + threadIdx.x;
    unsigned act = __ballot_sync(0xffffffffu, i < NN);
    if (i < NN) {
        int b = batch[i];
        unsigned m = __match_any_sync(act, b);
        int leader = __ffs(m) - 1;
        if ((threadIdx.x & 31) == leader)
            atomicAdd(&gcnt[b], (float)__popc(m));
    }
}

__global__ void k_pool64(const float* __restrict__ h2, const int* __restrict__ batch,
                         float* __restrict__ gsum) {
    constexpr int RB = 256;
    __shared__ float sm[4][64];
    __shared__ int s_gmin, s_ngr;
    int base = blockIdx.x * RB;
    int nrows = NN - base; if (nrows > RB) nrows = RB;
    int tid = threadIdx.x;
    if (tid == 0) {
        int gmin = batch[base];
        int gmax = batch[base + nrows - 1];
        s_gmin = gmin; s_ngr = gmax - gmin + 1;
    }
    for (int i = tid; i < 4 * 64; i += 256) ((float*)sm)[i] = 0.f;
    __syncthreads();
    int gmin = s_gmin, ngr = s_ngr;
    int col = tid & 63, strip = tid >> 6;
    if (ngr <= 4) {
        int curg = -1; float acc = 0.f;
        for (int r = strip; r < nrows; r += 4) {
            int node = base + r;
            int g = batch[node];
            float v = h2[(size_t)node * 64 + col];
            if (g != curg) {
                if (curg >= 0) atomicAdd(&sm[curg - gmin][col], acc);
                curg = g; acc = v;
            } else acc += v;
        }
        if (curg >= 0) atomicAdd(&sm[curg - gmin][col], acc);
        __syncthreads();
        if (tid < 64)
            for (int s = 0; s < ngr; s++)
                atomicAdd(&gsum[(size_t)(gmin + s) * 64 + col], sm[s][col]);
    } else {
        for (int r = strip; r < nrows; r += 4) {
            int node = base + r;
            atomicAdd(&gsum[(size_t)batch[node] * 64 + col],
                      h2[(size_t)node * 64 + col]);
        }
    }
}

// ---------------- final: ge = (gsum/cnt)@Wf1+bf1 ; ic = ge@Wf2+bf2 ----------
__global__ void k_final2(const float* __restrict__ gsum, const float* __restrict__ gcnt,
                         const float* __restrict__ Wf1, const float* __restrict__ bf1,
                         const float* __restrict__ Wf2, const float* __restrict__ bf2,
                         float* __restrict__ out) {
    __shared__ float ge[NG * DENSE];
    int tid = threadIdx.x;                     // 256
    for (int idx = tid; idx < NG * DENSE; idx += 256) {
        int gg = idx >> 7, j = idx & 127;
        float inv = 1.0f / fmaxf(gcnt[gg], 1.0f);
        const float* pg = gsum + gg * 64;
        float a = 0.f;
#pragma unroll 8
        for (int c = 0; c < 64; c++)
            a += pg[c] * Wf1[c * DENSE + j];
        float v = a * inv + bf1[j];
        ge[idx] = v;
        out[idx] = v;
    }
    __syncthreads();
    if (tid < NG * LABELS) {
        int gg = tid >> 1, l = tid & 1;
        float s = bf2[l];
#pragma unroll 8
        for (int c = 0; c < DENSE; c++)
            s += ge[gg * DENSE + c] * Wf2[c * LABELS + l];
        out[NG * DENSE + 1 + tid] = s;
    }
    if (tid == 0) out[NG * DENSE] = 0.f;
}

// ---------------- launch ----------------------------------------------------
extern "C" void kernel_launch(void* const* d_in, const int* in_sizes, int n_in,
                              void* d_out, int out_size) {
    const float* x   = (const float*)d_in[0];
    const float* W1  = (const float*)d_in[1];
    const float* b1  = (const float*)d_in[2];
    const float* W2  = (const float*)d_in[3];
    const float* b2  = (const float*)d_in[4];
    const float* Wf1 = (const float*)d_in[5];
    const float* bf1 = (const float*)d_in[6];
    const float* Wf2 = (const float*)d_in[7];
    const float* bf2 = (const float*)d_in[8];
    const int* ei    = (const int*)d_in[9];
    const int* batch = (const int*)d_in[10];
    const int* src = ei;
    const int* dst = ei + EE;
    float* out = (float*)d_out;

    float *dis, *h1, *h2, *gsum, *gcnt;
    __nv_bfloat16* hb;
    int *deg, *rowptr, *nextptr, *partials, *csr;
    cudaGetSymbolAddress((void**)&dis,  g_dis);
    cudaGetSymbolAddress((void**)&deg,  g_deg);
    cudaGetSymbolAddress((void**)&rowptr, g_rowptr);
    cudaGetSymbolAddress((void**)&nextptr, g_nextptr);
    cudaGetSymbolAddress((void**)&partials, g_partials);
    cudaGetSymbolAddress((void**)&csr,  g_csr);
    cudaGetSymbolAddress((void**)&hb,   g_hb);
    cudaGetSymbolAddress((void**)&h1,   g_h1);
    cudaGetSymbolAddress((void**)&h2,   g_h2);
    cudaGetSymbolAddress((void**)&gsum, g_gsum);
    cudaGetSymbolAddress((void**)&gcnt, g_gcnt);

    const int TB = 256;
    const int nblkN = (NN + TB - 1) / TB;
    const int ew_grid = 148 * 16;
    const int gemm_blocks = (NN + 127) / 128;
    const int gather_blocks = (NN * 32 + TB - 1) / TB;

    // ---- CSR build + normalization (dis needed by gemm epilogue)
    k_zero_deg<<<nblkN, TB>>>(deg);
    k_deg_count<<<ew_grid, TB>>>(dst, deg);
    k_scan_block<<<NB_SCAN, SCAN_BLK>>>(deg, rowptr, partials);
    k_scan_partials<<<1, 256>>>(partials);
    k_scan_add<<<nblkN, TB>>>(rowptr, partials, nextptr, deg, dis);

    // ---- layer 1: hb = bf16((x@W1)*dis) ; h1 = relu(dn*(sum+self)+b1)
    k_gemm_tc<128><<<gemm_blocks, 256>>>(x, W1, dis, hb, NN);
    k_fill<<<ew_grid, TB>>>(src, dst, nextptr, csr);
    k_gather128s<<<gather_blocks, TB>>>(hb, dis, deg, rowptr, csr, b1, h1);

    // ---- layer 2
    k_gemm_tc<64><<<gemm_blocks, 256>>>(h1, W2, dis, hb, NN);
    k_gather64s<<<gather_blocks, TB>>>(hb, dis, deg, rowptr, csr, b2, h2);

    // ---- pooling (Wf1 folded) + head
    k_zero_pool<<<(NG * 64 + TB - 1) / TB, TB>>>(gsum, gcnt);
    k_count<<<nblkN, TB>>>(batch, gcnt);
    k_pool64<<<(NN + 255) / 256, 256>>>(h2, batch, gsum);
    k_final2<<<1, 256>>>(gsum, gcnt, Wf1, bf1, Wf2, bf2, out);
}